// round 2
// baseline (speedup 1.0000x reference)
#include <cuda_runtime.h>
#include <cstdint>

#define BATCH 4
#define A_TOT 76725
#define A_PAD 76800
#define NCLS  80
#define KCAND 512
#define MAXPC 100

// ---------------- scratch (device globals; no allocations allowed) ----------------
__device__ float  g_scores_t[(size_t)BATCH * NCLS * A_TOT];   // ~98 MB, [b][c][a]
__device__ float4 g_boxes[BATCH * A_TOT];                     // decoded [x,y,w,h]
__device__ float  g_cls_scores[BATCH * NCLS * MAXPC];
__device__ float4 g_cls_boxes[BATCH * NCLS * MAXPC];
__device__ float  g_dims[45 * 2];                             // per (level,k): w,h

// ---------------- helpers ----------------
__device__ __forceinline__ float sigmoid_f(float x) {
    if (x >= 0.f) { float z = expf(-x); return 1.f / (1.f + z); }
    float z = expf(x); return z / (1.f + z);
}

// bitonic sort, u64 descending, n power of two, blockDim threads
__device__ void bitonic_u64_desc(unsigned long long* key, int n) {
    for (int k = 2; k <= n; k <<= 1) {
        for (int j = k >> 1; j > 0; j >>= 1) {
            for (int idx = threadIdx.x; idx < n; idx += blockDim.x) {
                int p = idx ^ j;
                if (p > idx) {
                    unsigned long long a = key[idx], b = key[p];
                    bool up = ((idx & k) == 0);
                    bool sw = up ? (a < b) : (a > b);
                    if (sw) { key[idx] = b; key[p] = a; }
                }
            }
            __syncthreads();
        }
    }
}

// bitonic sort, u32 ascending
__device__ void bitonic_u32_asc(unsigned int* key, int n) {
    for (int k = 2; k <= n; k <<= 1) {
        for (int j = k >> 1; j > 0; j >>= 1) {
            for (int idx = threadIdx.x; idx < n; idx += blockDim.x) {
                int p = idx ^ j;
                if (p > idx) {
                    unsigned int a = key[idx], b = key[p];
                    bool up = ((idx & k) == 0);
                    bool sw = up ? (a > b) : (a < b);
                    if (sw) { key[idx] = b; key[p] = a; }
                }
            }
            __syncthreads();
        }
    }
}

// 4-pass radix select: returns T = K-th largest value's bits (all values >= 0 floats),
// *E_out = number of entries equal to T that belong to the top-K (taken by smallest idx).
__device__ unsigned radix_select_topk(const float* sc, int N, int Npad, int K,
                                      unsigned* hist, int* misc, int* E_out) {
    unsigned prefix = 0;
    int lane = threadIdx.x & 31;
    unsigned lt = (1u << lane) - 1u;
    for (int pass = 0; pass < 4; pass++) {
        int shift = 24 - 8 * pass;
        for (int i = threadIdx.x; i < 256; i += blockDim.x) hist[i] = 0;
        __syncthreads();
        unsigned himask = pass ? (0xFFFFFFFFu << (shift + 8)) : 0u;
        for (int i = threadIdx.x; i < Npad; i += blockDim.x) {
            unsigned u = 0; bool ok = false;
            if (i < N) { u = __float_as_uint(sc[i]); ok = (pass == 0) || ((u & himask) == prefix); }
            unsigned bk = ok ? ((u >> shift) & 0xFFu) : (0x200u + (unsigned)lane);
            unsigned peers = __match_any_sync(0xFFFFFFFFu, bk);
            if (ok && ((peers & lt) == 0u)) atomicAdd(&hist[bk], (unsigned)__popc(peers));
        }
        __syncthreads();
        if (threadIdx.x == 0) {
            int cum = 0, chosen = 0;
            for (int bb = 255; bb >= 0; bb--) {
                int h = (int)hist[bb];
                if (cum + h >= K) { chosen = bb; break; }
                cum += h;
            }
            misc[0] = chosen; misc[1] = cum;
        }
        __syncthreads();
        K -= misc[1];
        prefix |= ((unsigned)misc[0]) << shift;
        __syncthreads();
    }
    *E_out = K;
    return prefix;
}

// ---------------- kernel 0: anchor dims table (double precision, matches numpy) ----------------
__global__ void k_dims() {
    int t = threadIdx.x;
    if (t < 45) {
        int lvl = t / 9, k = t % 9;
        int ri = k / 3, si = k % 3;
        double r = (ri == 0) ? 0.5 : (ri == 1 ? 1.0 : 2.0);
        double s = pow(2.0, (double)si / 3.0);
        double side = (double)(1 << (lvl + 5));       // 2^(level+2), level = lvl+3
        double area = side * side;
        double ah = sqrt(area / r);
        double aw = area / ah;
        g_dims[t * 2 + 0] = (float)(s * aw);
        g_dims[t * 2 + 1] = (float)(s * ah);
    }
}

// ---------------- kernel 1: decode + score transpose ----------------
__global__ void k_decode(const float* __restrict__ pred) {
    __shared__ float tile[32 * 85];
    int b = blockIdx.y;
    int a0 = blockIdx.x * 32;
    int nA = min(32, A_TOT - a0);
    const float* base = pred + ((size_t)b * A_TOT + a0) * 84;
    int cnt = nA * 84;
    for (int i = threadIdx.x; i < cnt; i += 256) {
        int la = i / 84, ch = i - la * 84;
        tile[la * 85 + ch] = base[i];
    }
    __syncthreads();
    // transposed sigmoid scores
    for (int i = threadIdx.x; i < NCLS * 32; i += 256) {
        int c = i >> 5, la = i & 31;
        if (la < nA) {
            g_scores_t[((size_t)(b * NCLS + c)) * A_TOT + a0 + la] = sigmoid_f(tile[la * 85 + c]);
        }
    }
    // decoded boxes
    if (threadIdx.x < 32) {
        int la = threadIdx.x;
        if (la < nA) {
            int a = a0 + la;
            int lvl, rem, fw;
            if      (a < 57600) { lvl = 0; rem = a;          fw = 80; }
            else if (a < 72000) { lvl = 1; rem = a - 57600;  fw = 40; }
            else if (a < 75600) { lvl = 2; rem = a - 72000;  fw = 20; }
            else if (a < 76500) { lvl = 3; rem = a - 75600;  fw = 10; }
            else                { lvl = 4; rem = a - 76500;  fw = 5;  }
            int k = rem % 9, cell = rem / 9;
            int x = cell % fw, y = cell / fw;
            float stride = (float)(8 << lvl);
            float acx = ((float)x + 0.5f) * stride;
            float acy = ((float)y + 0.5f) * stride;
            float aw = g_dims[(lvl * 9 + k) * 2 + 0];
            float ah = g_dims[(lvl * 9 + k) * 2 + 1];
            float bp0 = tile[la * 85 + 80] * 0.1f;
            float bp1 = tile[la * 85 + 81] * 0.1f;
            float bp2 = tile[la * 85 + 82] * 0.2f;
            float bp3 = tile[la * 85 + 83] * 0.2f;
            float4 o;
            o.x = bp0 * aw + acx;
            o.y = bp1 * ah + acy;
            o.z = expf(bp2) * aw;
            o.w = expf(bp3) * ah;
            g_boxes[b * A_TOT + a] = o;
        }
    }
}

// ---------------- kernel 2: per-(b,c) top-512 + NMS + per-class top-100 ----------------
__global__ void __launch_bounds__(256) k_nms() {
    __shared__ unsigned int sh_mask[KCAND * 16];       // 32 KB; overlays selection scratch
    __shared__ unsigned long long sh_key[KCAND];       // 4 KB
    __shared__ float sh_c0[KCAND], sh_c1[KCAND], sh_c2[KCAND], sh_c3[KCAND], sh_ar[KCAND];
    __shared__ unsigned int sh_keep[16];
    __shared__ int sh_misc[8];

    unsigned int* hist     = sh_mask;          // [0,256)
    unsigned int* cand_sc  = sh_mask + 256;    // [256,768)
    unsigned int* cand_idx = sh_mask + 768;    // [768,1280)
    unsigned int* tie_idx  = sh_mask + 1280;   // [1280,1792)

    int bc = blockIdx.x;
    int b = bc / NCLS, c = bc % NCLS;
    const float* sc = g_scores_t + (size_t)bc * A_TOT;

    int lane = threadIdx.x & 31;
    unsigned lt = (1u << lane) - 1u;

    // ---- top-512 threshold ----
    int E;
    unsigned T = radix_select_topk(sc, A_TOT, A_PAD, KCAND, hist, sh_misc, &E);
    int G = KCAND - E;

    // ---- collect ----
    if (threadIdx.x == 0) { sh_misc[2] = 0; sh_misc[3] = 0; }
    __syncthreads();
    for (int i = threadIdx.x; i < A_PAD; i += 256) {
        unsigned u = 0; bool inb = i < A_TOT;
        if (inb) u = __float_as_uint(sc[i]);
        bool gt = inb && (u > T);
        bool eq = inb && (u == T);
        unsigned bg = __ballot_sync(0xFFFFFFFFu, gt);
        if (gt) {
            int ldr = __ffs(bg) - 1;
            int bs;
            if (lane == ldr) bs = atomicAdd(&sh_misc[2], __popc(bg));
            bs = __shfl_sync(bg, bs, ldr);
            int pos = bs + __popc(bg & lt);
            if (pos < KCAND) { cand_sc[pos] = u; cand_idx[pos] = (unsigned)i; }
        }
        unsigned be = __ballot_sync(0xFFFFFFFFu, eq);
        if (eq) {
            int ldr = __ffs(be) - 1;
            int bs;
            if (lane == ldr) bs = atomicAdd(&sh_misc[3], __popc(be));
            bs = __shfl_sync(be, bs, ldr);
            int pos = bs + __popc(be & lt);
            if (pos < KCAND) tie_idx[pos] = (unsigned)i;
        }
    }
    __syncthreads();
    int nt = sh_misc[3];
    for (int s = threadIdx.x; s < KCAND; s += 256)
        if (s >= nt) tie_idx[s] = 0xFFFFFFFFu;
    __syncthreads();
    bitonic_u32_asc(tie_idx, KCAND);   // smallest tie indices first (stable top_k)

    // ---- build sort keys: (score_bits<<32) | ~idx ; sort descending ----
    for (int s = threadIdx.x; s < KCAND; s += 256) {
        unsigned long long key;
        if (s < G) key = (((unsigned long long)cand_sc[s]) << 32) | (unsigned)(~cand_idx[s]);
        else       key = (((unsigned long long)T) << 32)          | (unsigned)(~tie_idx[s - G]);
        sh_key[s] = key;
    }
    __syncthreads();
    bitonic_u64_desc(sh_key, KCAND);

    // ---- gather boxes ----
    for (int s = threadIdx.x; s < KCAND; s += 256) {
        unsigned idx = ~((unsigned)(sh_key[s] & 0xFFFFFFFFull));
        float4 bx = g_boxes[b * A_TOT + (int)idx];
        sh_c0[s] = bx.x; sh_c1[s] = bx.y; sh_c2[s] = bx.z; sh_c3[s] = bx.w;
        sh_ar[s] = fmaxf(bx.z - bx.x, 0.f) * fmaxf(bx.w - bx.y, 0.f);
    }
    __syncthreads();

    // ---- IoU suppression bitmask: mask[i][w] bits for j>i with iou>0.5 ----
    for (int task = threadIdx.x; task < KCAND * 16; task += 256) {
        int w = task >> 9;           // word (shared across warp lanes)
        int i = task & 511;          // candidate i (consecutive across lanes)
        int j0 = w << 5;
        unsigned bits = 0;
        if (j0 + 31 > i) {
            float iy1 = sh_c0[i], ix1 = sh_c1[i], iy2 = sh_c2[i], ix2 = sh_c3[i], ia = sh_ar[i];
            #pragma unroll 8
            for (int jj = 0; jj < 32; jj++) {
                int j = j0 + jj;
                if (j > i) {
                    float ih = fmaxf(fminf(iy2, sh_c2[j]) - fmaxf(iy1, sh_c0[j]), 0.f);
                    float iw = fmaxf(fminf(ix2, sh_c3[j]) - fmaxf(ix1, sh_c1[j]), 0.f);
                    float inter = ih * iw;
                    float un = ia + sh_ar[j] - inter;
                    float iou = (un > 0.f) ? (inter / un) : 0.f;
                    if (iou > 0.5f) bits |= (1u << jj);
                }
            }
        }
        sh_mask[i * 16 + w] = bits;
    }
    __syncthreads();

    // ---- greedy NMS: warp 0, lanes 0..15 own 32-bit keep words in registers ----
    if (threadIdx.x < 16) {
        unsigned keep = 0;
        for (int t = 0; t < 32; t++) {
            float scf = __uint_as_float((unsigned)(sh_key[threadIdx.x * 32 + t] >> 32));
            if (scf > 0.05f) keep |= (1u << t);
        }
        for (int i = 0; i < KCAND; i++) {
            unsigned m = sh_mask[i * 16 + threadIdx.x];
            unsigned kw = __shfl_sync(0x0000FFFFu, keep, i >> 5);
            if ((kw >> (i & 31)) & 1u) keep &= ~m;
        }
        sh_keep[threadIdx.x] = keep;
    }
    __syncthreads();

    // ---- emit per-class top-100: kept in order, then suppressed in order (== top_k(kept_s,100)) ----
    int nk = 0;
    for (int w = 0; w < 16; w++) nk += __popc(sh_keep[w]);
    for (int s = threadIdx.x; s < KCAND; s += 256) {
        int w = s >> 5, bpos = s & 31;
        unsigned kw = sh_keep[w];
        bool kept = (kw >> bpos) & 1u;
        int pre = 0;
        for (int q = 0; q < w; q++) pre += __popc(sh_keep[q]);
        pre += __popc(kw & ((1u << bpos) - 1u));
        int r = kept ? pre : (nk + (s - pre));
        if (r < MAXPC) {
            float scf = __uint_as_float((unsigned)(sh_key[s] >> 32));
            int ob = (b * NCLS + c) * MAXPC + r;
            g_cls_scores[ob] = kept ? scf : 0.0f;
            float4 bx; bx.x = sh_c0[s]; bx.y = sh_c1[s]; bx.z = sh_c2[s]; bx.w = sh_c3[s];
            g_cls_boxes[ob] = bx;
        }
    }
}

// ---------------- kernel 3: combine (per batch): top-100 of 8000, clip/mask/write ----------------
__global__ void __launch_bounds__(256) k_combine(float* __restrict__ out, int out_size) {
    __shared__ unsigned int csh[256 + 128 + 128 + 512];
    __shared__ unsigned long long ckey[128];
    __shared__ int cmisc[8];
    unsigned int* hist     = csh;          // 256
    unsigned int* cand_sc  = csh + 256;    // 128
    unsigned int* cand_idx = csh + 384;    // 128
    unsigned int* tie      = csh + 512;    // 512

    int b = blockIdx.x;
    const float* sc = g_cls_scores + b * (NCLS * MAXPC);
    const int N = NCLS * MAXPC;      // 8000
    const int NP = 8192;

    int lane = threadIdx.x & 31;
    unsigned lt = (1u << lane) - 1u;

    int E;
    unsigned T = radix_select_topk(sc, N, NP, MAXPC, hist, cmisc, &E);
    int G = MAXPC - E;

    if (threadIdx.x == 0) { cmisc[2] = 0; cmisc[3] = 0; cmisc[4] = 0; }
    __syncthreads();
    for (int i = threadIdx.x; i < NP; i += 256) {
        unsigned u = 0; bool inb = i < N;
        if (inb) u = __float_as_uint(sc[i]);
        bool gt = inb && (u > T);
        bool eq = inb && (u == T);
        unsigned bg = __ballot_sync(0xFFFFFFFFu, gt);
        if (gt) {
            int ldr = __ffs(bg) - 1;
            int bs;
            if (lane == ldr) bs = atomicAdd(&cmisc[2], __popc(bg));
            bs = __shfl_sync(bg, bs, ldr);
            int pos = bs + __popc(bg & lt);
            if (pos < 128) { cand_sc[pos] = u; cand_idx[pos] = (unsigned)i; }
        }
        unsigned be = __ballot_sync(0xFFFFFFFFu, eq);
        if (eq) {
            int ldr = __ffs(be) - 1;
            int bs;
            if (lane == ldr) bs = atomicAdd(&cmisc[3], __popc(be));
            bs = __shfl_sync(be, bs, ldr);
            int pos = bs + __popc(be & lt);
            if (pos < 512) tie[pos] = (unsigned)i;
        }
    }
    __syncthreads();
    int nt = cmisc[3];
    for (int s = threadIdx.x; s < 512; s += 256)
        if (s >= nt) tie[s] = 0xFFFFFFFFu;
    __syncthreads();
    bitonic_u32_asc(tie, 512);

    for (int s = threadIdx.x; s < 128; s += 256) {
        unsigned long long key;
        if (s < G)           key = (((unsigned long long)cand_sc[s]) << 32) | (unsigned)(~cand_idx[s]);
        else if (s < MAXPC)  key = (((unsigned long long)T) << 32)          | (unsigned)(~tie[s - G]);
        else                 key = 0ull;
        ckey[s] = key;
    }
    __syncthreads();
    bitonic_u64_desc(ckey, 128);

    int r = threadIdx.x;
    if (r < MAXPC) {
        unsigned long long kk = ckey[r];
        float s = __uint_as_float((unsigned)(kk >> 32));
        bool valid = s > 0.0f;
        float b0 = 0.f, b1 = 0.f, b2 = 0.f, b3 = 0.f, cls = 0.f, so = 0.f;
        if (valid) {
            unsigned f = ~((unsigned)(kk & 0xFFFFFFFFull));
            int ci = (int)f / MAXPC;
            float4 bb = g_cls_boxes[b * N + (int)f];
            b0 = fminf(fmaxf(bb.x, 0.f), 1.f);
            b1 = fminf(fmaxf(bb.y, 0.f), 1.f);
            b2 = fminf(fmaxf(bb.z, 0.f), 1.f);
            b3 = fminf(fmaxf(bb.w, 0.f), 1.f);
            cls = (float)ci;
            so = s;
            atomicAdd(&cmisc[4], 1);
        }
        int ob = (b * MAXPC + r) * 4;
        if (ob + 3 < out_size) {
            out[ob + 0] = b0; out[ob + 1] = b1; out[ob + 2] = b2; out[ob + 3] = b3;
        }
        int os = BATCH * MAXPC * 4 + b * MAXPC + r;                 // scores @1600
        if (os < out_size) out[os] = so;
        int oc = BATCH * MAXPC * 4 + BATCH * MAXPC + b * MAXPC + r; // classes @2000
        if (oc < out_size) out[oc] = cls;
    }
    __syncthreads();
    if (threadIdx.x == 0) {
        int ov = BATCH * MAXPC * 4 + 2 * BATCH * MAXPC + b;          // valid @2400
        if (ov < out_size) out[ov] = (float)cmisc[4];
    }
}

// ---------------- launch ----------------
extern "C" void kernel_launch(void* const* d_in, const int* in_sizes, int n_in,
                              void* d_out, int out_size) {
    const float* pred;
    if (n_in >= 2 && in_sizes[0] == BATCH * A_TOT * 84) pred = (const float*)d_in[0];
    else                                                pred = (const float*)d_in[1];
    float* out = (float*)d_out;

    k_dims<<<1, 64>>>();
    k_decode<<<dim3((A_TOT + 31) / 32, BATCH), 256>>>(pred);
    k_nms<<<BATCH * NCLS, 256>>>();
    k_combine<<<BATCH, 256>>>(out, out_size);
}

// round 3
// speedup vs baseline: 3.1904x; 3.1904x over previous
#include <cuda_runtime.h>
#include <cstdint>

#define BATCH 4
#define A_TOT 76725
#define A_PAD 76800
#define NCLS  80
#define KCAND 512
#define MAXPC 100
#define CAP   1024
// logit(0.91) = ln(0.91/0.09)
#define LOGIT_T0 2.3136349f

// ---------------- scratch (device globals; no allocations allowed) ----------------
__device__ float4 g_boxes[BATCH * A_TOT];                     // decoded [x,y,w,h]
__device__ uint2  g_cand[BATCH * NCLS * CAP];                 // (score_bits, anchor_idx)
__device__ int    g_cand_cnt[BATCH * NCLS];
__device__ float  g_cls_scores[BATCH * NCLS * MAXPC];
__device__ float4 g_cls_boxes[BATCH * NCLS * MAXPC];
__device__ float  g_dims[45 * 2];                             // per (level,k): w,h

// ---------------- helpers ----------------
__device__ __forceinline__ float sigmoid_f(float x) {
    if (x >= 0.f) { float z = expf(-x); return 1.f / (1.f + z); }
    float z = expf(x); return z / (1.f + z);
}

__device__ void bitonic_u64_desc(unsigned long long* key, int n) {
    for (int k = 2; k <= n; k <<= 1) {
        for (int j = k >> 1; j > 0; j >>= 1) {
            for (int idx = threadIdx.x; idx < n; idx += blockDim.x) {
                int p = idx ^ j;
                if (p > idx) {
                    unsigned long long a = key[idx], b = key[p];
                    bool up = ((idx & k) == 0);
                    bool sw = up ? (a < b) : (a > b);
                    if (sw) { key[idx] = b; key[p] = a; }
                }
            }
            __syncthreads();
        }
    }
}

__device__ void bitonic_u32_asc(unsigned int* key, int n) {
    for (int k = 2; k <= n; k <<= 1) {
        for (int j = k >> 1; j > 0; j >>= 1) {
            for (int idx = threadIdx.x; idx < n; idx += blockDim.x) {
                int p = idx ^ j;
                if (p > idx) {
                    unsigned int a = key[idx], b = key[p];
                    bool up = ((idx & k) == 0);
                    bool sw = up ? (a > b) : (a < b);
                    if (sw) { key[idx] = b; key[p] = a; }
                }
            }
            __syncthreads();
        }
    }
}

// warp-parallel "pick threshold bucket" over a 256-bin shared histogram.
// Writes misc[0]=chosen bin, misc[1]=count strictly above chosen bin.
__device__ __forceinline__ void pick_bucket(unsigned* hist, int* misc, int K) {
    if (threadIdx.x < 32) {
        int l = threadIdx.x;
        int base = 255 - l * 8;
        unsigned hv[8]; unsigned t = 0;
        #pragma unroll
        for (int q = 0; q < 8; q++) { hv[q] = hist[base - q]; t += hv[q]; }
        unsigned p = t;
        #pragma unroll
        for (int o = 1; o < 32; o <<= 1) {
            unsigned v = __shfl_up_sync(0xFFFFFFFFu, p, o);
            if (l >= o) p += v;
        }
        unsigned excl = p - t;   // total in lanes above (higher bins)
        bool has = (excl < (unsigned)K) && ((unsigned)K <= excl + t);
        unsigned bal = __ballot_sync(0xFFFFFFFFu, has);
        int ldr = __ffs(bal) - 1;
        if (l == ldr) {
            unsigned cum = excl; int chosen = base;
            #pragma unroll
            for (int q = 0; q < 8; q++) {
                if (cum + hv[q] >= (unsigned)K) { chosen = base - q; break; }
                cum += hv[q];
            }
            misc[0] = chosen; misc[1] = (int)cum;
        }
    }
    __syncthreads();
}

// 4-pass radix select over strided values (optionally sigmoid-transformed).
// Returns bits of K-th largest value; *E_out = #ties belonging to top-K.
__device__ unsigned radix_select_topk(const float* base, int stride, bool sig,
                                      int N, int Npad, int K,
                                      unsigned* hist, int* misc, int* E_out) {
    unsigned prefix = 0;
    int lane = threadIdx.x & 31;
    unsigned lt = (1u << lane) - 1u;
    for (int pass = 0; pass < 4; pass++) {
        int shift = 24 - 8 * pass;
        for (int i = threadIdx.x; i < 256; i += blockDim.x) hist[i] = 0;
        __syncthreads();
        unsigned himask = pass ? (0xFFFFFFFFu << (shift + 8)) : 0u;
        for (int i = threadIdx.x; i < Npad; i += blockDim.x) {
            unsigned u = 0; bool ok = false;
            if (i < N) {
                float v = base[(size_t)i * stride];
                if (sig) v = sigmoid_f(v);
                u = __float_as_uint(v);
                ok = (pass == 0) || ((u & himask) == prefix);
            }
            unsigned bk = ok ? ((u >> shift) & 0xFFu) : (0x200u + (unsigned)lane);
            unsigned peers = __match_any_sync(0xFFFFFFFFu, bk);
            if (ok && ((peers & lt) == 0u)) atomicAdd(&hist[bk], (unsigned)__popc(peers));
        }
        __syncthreads();
        pick_bucket(hist, misc, K);
        K -= misc[1];
        prefix |= ((unsigned)misc[0]) << shift;
        __syncthreads();
    }
    *E_out = K;
    return prefix;
}

// ---------------- kernel 0: init (anchor dims in double, counters reset) ----------------
__global__ void k_init() {
    int t = threadIdx.x;
    if (t < 45) {
        int lvl = t / 9, k = t % 9;
        int ri = k / 3, si = k % 3;
        double r = (ri == 0) ? 0.5 : (ri == 1 ? 1.0 : 2.0);
        double s = pow(2.0, (double)si / 3.0);
        double side = (double)(1 << (lvl + 5));
        double area = side * side;
        double ah = sqrt(area / r);
        double aw = area / ah;
        g_dims[t * 2 + 0] = (float)(s * aw);
        g_dims[t * 2 + 1] = (float)(s * ah);
    }
    int ci = t - 64;
    if (ci >= 0 && ci < BATCH * NCLS) g_cand_cnt[ci] = 0;
}

// ---------------- kernel 1: decode boxes + compact candidate extraction ----------------
__global__ void __launch_bounds__(256) k_decode(const float* __restrict__ pred) {
    __shared__ float tile[32 * 85];
    int b = blockIdx.y;
    int a0 = blockIdx.x * 32;
    int nA = min(32, A_TOT - a0);
    const float* base = pred + ((size_t)b * A_TOT + a0) * 84;
    int cnt4 = (nA * 84) >> 2;
    const float4* base4 = (const float4*)base;
    for (int v = threadIdx.x; v < cnt4; v += 256) {
        float4 q = base4[v];
        int i0 = v * 4;
        int la = i0 / 84, ch = i0 - la * 84;
        // 84 % 4 == 0, so a float4 never crosses an anchor-row boundary
        float* dst = &tile[la * 85 + ch];
        dst[0] = q.x; dst[1] = q.y; dst[2] = q.z; dst[3] = q.w;
    }
    __syncthreads();

    int lane = threadIdx.x & 31;
    unsigned lt = (1u << lane) - 1u;

    // candidate extraction: each warp-iteration covers (one class, 32 anchors)
    for (int i = threadIdx.x; i < NCLS * 32; i += 256) {
        int c = i >> 5, la = i & 31;
        float v = tile[la * 85 + c];
        bool cand = (la < nA) && (v > LOGIT_T0);
        unsigned m = __ballot_sync(0xFFFFFFFFu, cand);
        if (m) {
            int ldr = __ffs(m) - 1;
            int bs = 0;
            if (lane == ldr) bs = atomicAdd(&g_cand_cnt[b * NCLS + c], __popc(m));
            bs = __shfl_sync(0xFFFFFFFFu, bs, ldr);
            if (cand) {
                int slot = bs + __popc(m & lt);
                if (slot < CAP) {
                    g_cand[(b * NCLS + c) * CAP + slot] =
                        make_uint2(__float_as_uint(sigmoid_f(v)), (unsigned)(a0 + la));
                }
            }
        }
    }

    // decoded boxes (one warp)
    if (threadIdx.x < 32) {
        int la = threadIdx.x;
        if (la < nA) {
            int a = a0 + la;
            int lvl, rem, fw;
            if      (a < 57600) { lvl = 0; rem = a;          fw = 80; }
            else if (a < 72000) { lvl = 1; rem = a - 57600;  fw = 40; }
            else if (a < 75600) { lvl = 2; rem = a - 72000;  fw = 20; }
            else if (a < 76500) { lvl = 3; rem = a - 75600;  fw = 10; }
            else                { lvl = 4; rem = a - 76500;  fw = 5;  }
            int k = rem % 9, cell = rem / 9;
            int x = cell % fw, y = cell / fw;
            float stride = (float)(8 << lvl);
            float acx = ((float)x + 0.5f) * stride;
            float acy = ((float)y + 0.5f) * stride;
            float aw = g_dims[(lvl * 9 + k) * 2 + 0];
            float ah = g_dims[(lvl * 9 + k) * 2 + 1];
            float bp0 = tile[la * 85 + 80] * 0.1f;
            float bp1 = tile[la * 85 + 81] * 0.1f;
            float bp2 = tile[la * 85 + 82] * 0.2f;
            float bp3 = tile[la * 85 + 83] * 0.2f;
            float4 o;
            o.x = bp0 * aw + acx;
            o.y = bp1 * ah + acy;
            o.z = expf(bp2) * aw;
            o.w = expf(bp3) * ah;
            g_boxes[b * A_TOT + a] = o;
        }
    }
}

// ---------------- kernel 2: per-(b,c) top-512 + NMS + per-class top-100 ----------------
__global__ void __launch_bounds__(256) k_nms(const float* __restrict__ pred) {
    __shared__ __align__(16) unsigned int sh_mask[KCAND * 16];  // 32 KB (overlaid scratch)
    __shared__ unsigned long long sh_key[KCAND];                // 4 KB
    __shared__ float sh_c0[KCAND], sh_c1[KCAND], sh_c2[KCAND], sh_c3[KCAND], sh_ar[KCAND];
    __shared__ unsigned int sh_keep[16];
    __shared__ int sh_misc[8];

    int bc = blockIdx.x;
    int b = bc / NCLS, c = bc % NCLS;
    int lane = threadIdx.x & 31;
    unsigned lt = (1u << lane) - 1u;

    int n = g_cand_cnt[bc];

    if (n >= KCAND && n <= CAP) {
        // -------- fast path: sort the <=1024 prefiltered candidates --------
        unsigned long long* buf = (unsigned long long*)sh_mask;   // 1024 u64 = 8 KB
        for (int s = threadIdx.x; s < CAP; s += 256) {
            unsigned long long key = 0ull;
            if (s < n) {
                uint2 r = g_cand[bc * CAP + s];
                key = (((unsigned long long)r.x) << 32) | (unsigned)(~r.y);
            }
            buf[s] = key;
        }
        __syncthreads();
        bitonic_u64_desc(buf, CAP);
        for (int s = threadIdx.x; s < KCAND; s += 256) sh_key[s] = buf[s];
        __syncthreads();
    } else {
        // -------- fallback (statistically never taken; exact & correct) --------
        unsigned int* hist     = sh_mask;
        unsigned int* cand_sc  = sh_mask + 256;
        unsigned int* cand_idx = sh_mask + 768;
        unsigned int* tie_idx  = sh_mask + 1280;
        const float* sbase = pred + (size_t)b * A_TOT * 84 + c;

        int E;
        unsigned T = radix_select_topk(sbase, 84, true, A_TOT, A_PAD, KCAND, hist, sh_misc, &E);
        int G = KCAND - E;

        if (threadIdx.x == 0) { sh_misc[2] = 0; sh_misc[3] = 0; }
        __syncthreads();
        for (int i = threadIdx.x; i < A_PAD; i += 256) {
            unsigned u = 0; bool inb = i < A_TOT;
            if (inb) u = __float_as_uint(sigmoid_f(sbase[(size_t)i * 84]));
            bool gt = inb && (u > T);
            bool eq = inb && (u == T);
            unsigned bg = __ballot_sync(0xFFFFFFFFu, gt);
            if (bg) {
                int ldr = __ffs(bg) - 1; int bs = 0;
                if (lane == ldr && gt) bs = atomicAdd(&sh_misc[2], __popc(bg));
                bs = __shfl_sync(0xFFFFFFFFu, bs, ldr);
                if (gt) {
                    int pos = bs + __popc(bg & lt);
                    if (pos < KCAND) { cand_sc[pos] = u; cand_idx[pos] = (unsigned)i; }
                }
            }
            unsigned be = __ballot_sync(0xFFFFFFFFu, eq);
            if (be) {
                int ldr = __ffs(be) - 1; int bs = 0;
                if (lane == ldr && eq) bs = atomicAdd(&sh_misc[3], __popc(be));
                bs = __shfl_sync(0xFFFFFFFFu, bs, ldr);
                if (eq) {
                    int pos = bs + __popc(be & lt);
                    if (pos < KCAND) tie_idx[pos] = (unsigned)i;
                }
            }
        }
        __syncthreads();
        int nt = sh_misc[3];
        for (int s = threadIdx.x; s < KCAND; s += 256)
            if (s >= nt) tie_idx[s] = 0xFFFFFFFFu;
        __syncthreads();
        bitonic_u32_asc(tie_idx, KCAND);
        for (int s = threadIdx.x; s < KCAND; s += 256) {
            unsigned long long key;
            if (s < G) key = (((unsigned long long)cand_sc[s]) << 32) | (unsigned)(~cand_idx[s]);
            else       key = (((unsigned long long)T) << 32)          | (unsigned)(~tie_idx[s - G]);
            sh_key[s] = key;
        }
        __syncthreads();
        bitonic_u64_desc(sh_key, KCAND);
    }

    // ---- gather boxes ----
    for (int s = threadIdx.x; s < KCAND; s += 256) {
        unsigned idx = ~((unsigned)(sh_key[s] & 0xFFFFFFFFull));
        float4 bx = g_boxes[b * A_TOT + (int)idx];
        sh_c0[s] = bx.x; sh_c1[s] = bx.y; sh_c2[s] = bx.z; sh_c3[s] = bx.w;
        sh_ar[s] = fmaxf(bx.z - bx.x, 0.f) * fmaxf(bx.w - bx.y, 0.f);
    }
    __syncthreads();

    // ---- IoU suppression bitmask ----
    for (int task = threadIdx.x; task < KCAND * 16; task += 256) {
        int w = task >> 9;
        int i = task & 511;
        int j0 = w << 5;
        unsigned bits = 0;
        if (j0 + 31 > i) {
            float iy1 = sh_c0[i], ix1 = sh_c1[i], iy2 = sh_c2[i], ix2 = sh_c3[i], ia = sh_ar[i];
            #pragma unroll 8
            for (int jj = 0; jj < 32; jj++) {
                int j = j0 + jj;
                if (j > i) {
                    float ih = fmaxf(fminf(iy2, sh_c2[j]) - fmaxf(iy1, sh_c0[j]), 0.f);
                    float iw = fmaxf(fminf(ix2, sh_c3[j]) - fmaxf(ix1, sh_c1[j]), 0.f);
                    float inter = ih * iw;
                    float un = ia + sh_ar[j] - inter;
                    float iou = (un > 0.f) ? (inter / un) : 0.f;
                    if (iou > 0.5f) bits |= (1u << jj);
                }
            }
        }
        sh_mask[i * 16 + w] = bits;
    }
    __syncthreads();

    // ---- greedy NMS: lanes 0..15 hold keep words ----
    if (threadIdx.x < 16) {
        unsigned keep = 0;
        for (int t = 0; t < 32; t++) {
            float scf = __uint_as_float((unsigned)(sh_key[threadIdx.x * 32 + t] >> 32));
            if (scf > 0.05f) keep |= (1u << t);
        }
        for (int i = 0; i < KCAND; i++) {
            unsigned m = sh_mask[i * 16 + threadIdx.x];
            unsigned kw = __shfl_sync(0x0000FFFFu, keep, i >> 5);
            if ((kw >> (i & 31)) & 1u) keep &= ~m;
        }
        sh_keep[threadIdx.x] = keep;
    }
    __syncthreads();

    // ---- emit per-class top-100 (kept in score order, then suppressed) ----
    int nk = 0;
    for (int w = 0; w < 16; w++) nk += __popc(sh_keep[w]);
    for (int s = threadIdx.x; s < KCAND; s += 256) {
        int w = s >> 5, bpos = s & 31;
        unsigned kw = sh_keep[w];
        bool kept = (kw >> bpos) & 1u;
        int pre = 0;
        for (int q = 0; q < w; q++) pre += __popc(sh_keep[q]);
        pre += __popc(kw & ((1u << bpos) - 1u));
        int r = kept ? pre : (nk + (s - pre));
        if (r < MAXPC) {
            float scf = __uint_as_float((unsigned)(sh_key[s] >> 32));
            int ob = (b * NCLS + c) * MAXPC + r;
            g_cls_scores[ob] = kept ? scf : 0.0f;
            float4 bx; bx.x = sh_c0[s]; bx.y = sh_c1[s]; bx.z = sh_c2[s]; bx.w = sh_c3[s];
            g_cls_boxes[ob] = bx;
        }
    }
}

// ---------------- kernel 3: combine (per batch) ----------------
__global__ void __launch_bounds__(256) k_combine(float* __restrict__ out, int out_size) {
    __shared__ unsigned int csh[256 + 128 + 128 + 512];
    __shared__ unsigned long long ckey[128];
    __shared__ int cmisc[8];
    unsigned int* hist     = csh;
    unsigned int* cand_sc  = csh + 256;
    unsigned int* cand_idx = csh + 384;
    unsigned int* tie      = csh + 512;

    int b = blockIdx.x;
    const float* sc = g_cls_scores + b * (NCLS * MAXPC);
    const int N = NCLS * MAXPC;
    const int NP = 8192;

    int lane = threadIdx.x & 31;
    unsigned lt = (1u << lane) - 1u;

    int E;
    unsigned T = radix_select_topk(sc, 1, false, N, NP, MAXPC, hist, cmisc, &E);
    int G = MAXPC - E;

    if (threadIdx.x == 0) { cmisc[2] = 0; cmisc[3] = 0; cmisc[4] = 0; }
    __syncthreads();
    for (int i = threadIdx.x; i < NP; i += 256) {
        unsigned u = 0; bool inb = i < N;
        if (inb) u = __float_as_uint(sc[i]);
        bool gt = inb && (u > T);
        bool eq = inb && (u == T);
        unsigned bg = __ballot_sync(0xFFFFFFFFu, gt);
        if (bg) {
            int ldr = __ffs(bg) - 1; int bs = 0;
            if (lane == ldr && gt) bs = atomicAdd(&cmisc[2], __popc(bg));
            bs = __shfl_sync(0xFFFFFFFFu, bs, ldr);
            if (gt) {
                int pos = bs + __popc(bg & lt);
                if (pos < 128) { cand_sc[pos] = u; cand_idx[pos] = (unsigned)i; }
            }
        }
        unsigned be = __ballot_sync(0xFFFFFFFFu, eq);
        if (be) {
            int ldr = __ffs(be) - 1; int bs = 0;
            if (lane == ldr && eq) bs = atomicAdd(&cmisc[3], __popc(be));
            bs = __shfl_sync(0xFFFFFFFFu, bs, ldr);
            if (eq) {
                int pos = bs + __popc(be & lt);
                if (pos < 512) tie[pos] = (unsigned)i;
            }
        }
    }
    __syncthreads();
    int nt = cmisc[3];
    for (int s = threadIdx.x; s < 512; s += 256)
        if (s >= nt) tie[s] = 0xFFFFFFFFu;
    __syncthreads();
    bitonic_u32_asc(tie, 512);

    for (int s = threadIdx.x; s < 128; s += 256) {
        unsigned long long key;
        if (s < G)           key = (((unsigned long long)cand_sc[s]) << 32) | (unsigned)(~cand_idx[s]);
        else if (s < MAXPC)  key = (((unsigned long long)T) << 32)          | (unsigned)(~tie[s - G]);
        else                 key = 0ull;
        ckey[s] = key;
    }
    __syncthreads();
    bitonic_u64_desc(ckey, 128);

    int r = threadIdx.x;
    if (r < MAXPC) {
        unsigned long long kk = ckey[r];
        float s = __uint_as_float((unsigned)(kk >> 32));
        bool valid = s > 0.0f;
        float b0 = 0.f, b1 = 0.f, b2 = 0.f, b3 = 0.f, cls = 0.f, so = 0.f;
        if (valid) {
            unsigned f = ~((unsigned)(kk & 0xFFFFFFFFull));
            int ci = (int)f / MAXPC;
            float4 bb = g_cls_boxes[b * N + (int)f];
            b0 = fminf(fmaxf(bb.x, 0.f), 1.f);
            b1 = fminf(fmaxf(bb.y, 0.f), 1.f);
            b2 = fminf(fmaxf(bb.z, 0.f), 1.f);
            b3 = fminf(fmaxf(bb.w, 0.f), 1.f);
            cls = (float)ci;
            so = s;
            atomicAdd(&cmisc[4], 1);
        }
        int ob = (b * MAXPC + r) * 4;
        if (ob + 3 < out_size) {
            out[ob + 0] = b0; out[ob + 1] = b1; out[ob + 2] = b2; out[ob + 3] = b3;
        }
        int os = BATCH * MAXPC * 4 + b * MAXPC + r;
        if (os < out_size) out[os] = so;
        int oc = BATCH * MAXPC * 4 + BATCH * MAXPC + b * MAXPC + r;
        if (oc < out_size) out[oc] = cls;
    }
    __syncthreads();
    if (threadIdx.x == 0) {
        int ov = BATCH * MAXPC * 4 + 2 * BATCH * MAXPC + b;
        if (ov < out_size) out[ov] = (float)cmisc[4];
    }
}

// ---------------- launch ----------------
extern "C" void kernel_launch(void* const* d_in, const int* in_sizes, int n_in,
                              void* d_out, int out_size) {
    const float* pred;
    if (n_in >= 2 && in_sizes[0] == BATCH * A_TOT * 84) pred = (const float*)d_in[0];
    else                                                pred = (const float*)d_in[1];
    float* out = (float*)d_out;

    k_init<<<1, 512>>>();
    k_decode<<<dim3((A_TOT + 31) / 32, BATCH), 256>>>(pred);
    k_nms<<<BATCH * NCLS, 256>>>(pred);
    k_combine<<<BATCH, 256>>>(out, out_size);
}

// round 5
// speedup vs baseline: 3.6551x; 1.1457x over previous
#include <cuda_runtime.h>
#include <cstdint>

#define BATCH 4
#define A_TOT 76725
#define A_PAD 76800
#define NCLS  80
#define KCAND 512
#define MAXPC 100
#define CAP   1024
// logit(0.91) = ln(0.91/0.09)
#define LOGIT_T0 2.3136349f

// ---------------- scratch (device globals; no allocations allowed) ----------------
__device__ float4 g_boxes[BATCH * A_TOT];                     // decoded [x,y,w,h]
__device__ uint2  g_cand[BATCH * NCLS * CAP];                 // (score_bits, anchor_idx)
__device__ int    g_cand_cnt[BATCH * NCLS];
__device__ float  g_cls_scores[BATCH * NCLS * MAXPC];
__device__ float4 g_cls_boxes[BATCH * NCLS * MAXPC];
__device__ float  g_dims[45 * 2];                             // per (level,k): w,h

// ---------------- helpers ----------------
__device__ __forceinline__ float sigmoid_f(float x) {
    if (x >= 0.f) { float z = expf(-x); return 1.f / (1.f + z); }
    float z = expf(x); return z / (1.f + z);
}

__device__ void bitonic_u64_desc(unsigned long long* key, int n) {
    for (int k = 2; k <= n; k <<= 1) {
        for (int j = k >> 1; j > 0; j >>= 1) {
            for (int idx = threadIdx.x; idx < n; idx += blockDim.x) {
                int p = idx ^ j;
                if (p > idx) {
                    unsigned long long a = key[idx], b = key[p];
                    bool up = ((idx & k) == 0);
                    bool sw = up ? (a < b) : (a > b);
                    if (sw) { key[idx] = b; key[p] = a; }
                }
            }
            __syncthreads();
        }
    }
}

__device__ void bitonic_u32_asc(unsigned int* key, int n) {
    for (int k = 2; k <= n; k <<= 1) {
        for (int j = k >> 1; j > 0; j >>= 1) {
            for (int idx = threadIdx.x; idx < n; idx += blockDim.x) {
                int p = idx ^ j;
                if (p > idx) {
                    unsigned int a = key[idx], b = key[p];
                    bool up = ((idx & k) == 0);
                    bool sw = up ? (a > b) : (a < b);
                    if (sw) { key[idx] = b; key[p] = a; }
                }
            }
            __syncthreads();
        }
    }
}

// warp-parallel "pick threshold bucket" over a 256-bin shared histogram.
__device__ __forceinline__ void pick_bucket(unsigned* hist, int* misc, int K) {
    if (threadIdx.x < 32) {
        int l = threadIdx.x;
        int base = 255 - l * 8;
        unsigned hv[8]; unsigned t = 0;
        #pragma unroll
        for (int q = 0; q < 8; q++) { hv[q] = hist[base - q]; t += hv[q]; }
        unsigned p = t;
        #pragma unroll
        for (int o = 1; o < 32; o <<= 1) {
            unsigned v = __shfl_up_sync(0xFFFFFFFFu, p, o);
            if (l >= o) p += v;
        }
        unsigned excl = p - t;
        bool has = (excl < (unsigned)K) && ((unsigned)K <= excl + t);
        unsigned bal = __ballot_sync(0xFFFFFFFFu, has);
        int ldr = __ffs(bal) - 1;
        if (l == ldr) {
            unsigned cum = excl; int chosen = base;
            #pragma unroll
            for (int q = 0; q < 8; q++) {
                if (cum + hv[q] >= (unsigned)K) { chosen = base - q; break; }
                cum += hv[q];
            }
            misc[0] = chosen; misc[1] = (int)cum;
        }
    }
    __syncthreads();
}

// 4-pass radix select; returns bits of K-th largest; *E_out = #ties in top-K.
__device__ unsigned radix_select_topk(const float* base, int stride, bool sig,
                                      int N, int Npad, int K,
                                      unsigned* hist, int* misc, int* E_out) {
    unsigned prefix = 0;
    int lane = threadIdx.x & 31;
    unsigned lt = (1u << lane) - 1u;
    for (int pass = 0; pass < 4; pass++) {
        int shift = 24 - 8 * pass;
        for (int i = threadIdx.x; i < 256; i += blockDim.x) hist[i] = 0;
        __syncthreads();
        unsigned himask = pass ? (0xFFFFFFFFu << (shift + 8)) : 0u;
        for (int i = threadIdx.x; i < Npad; i += blockDim.x) {
            unsigned u = 0; bool ok = false;
            if (i < N) {
                float v = base[(size_t)i * stride];
                if (sig) v = sigmoid_f(v);
                u = __float_as_uint(v);
                ok = (pass == 0) || ((u & himask) == prefix);
            }
            unsigned bk = ok ? ((u >> shift) & 0xFFu) : (0x200u + (unsigned)lane);
            unsigned peers = __match_any_sync(0xFFFFFFFFu, bk);
            if (ok && ((peers & lt) == 0u)) atomicAdd(&hist[bk], (unsigned)__popc(peers));
        }
        __syncthreads();
        pick_bucket(hist, misc, K);
        K -= misc[1];
        prefix |= ((unsigned)misc[0]) << shift;
        __syncthreads();
    }
    *E_out = K;
    return prefix;
}

// ---------------- kernel 0: init ----------------
__global__ void k_init() {
    int t = threadIdx.x;
    if (t < 45) {
        int lvl = t / 9, k = t % 9;
        int ri = k / 3, si = k % 3;
        double r = (ri == 0) ? 0.5 : (ri == 1 ? 1.0 : 2.0);
        double s = pow(2.0, (double)si / 3.0);
        double side = (double)(1 << (lvl + 5));
        double area = side * side;
        double ah = sqrt(area / r);
        double aw = area / ah;
        g_dims[t * 2 + 0] = (float)(s * aw);
        g_dims[t * 2 + 1] = (float)(s * ah);
    }
    int ci = t - 64;
    if (ci >= 0 && ci < BATCH * NCLS) g_cand_cnt[ci] = 0;
}

// ---------------- kernel 1: decode boxes + candidate extraction (64 anchors/block) ----------------
__global__ void __launch_bounds__(512) k_decode(const float* __restrict__ pred) {
    __shared__ float tile[64 * 85];
    int b = blockIdx.y;
    int a0 = blockIdx.x * 64;
    int nA = min(64, A_TOT - a0);
    const float* base = pred + ((size_t)b * A_TOT + a0) * 84;
    int cnt4 = (nA * 84) >> 2;
    const float4* base4 = (const float4*)base;
    for (int v = threadIdx.x; v < cnt4; v += 512) {
        float4 q = base4[v];
        int i0 = v * 4;
        int la = i0 / 84, ch = i0 - la * 84;
        float* dst = &tile[la * 85 + ch];
        dst[0] = q.x; dst[1] = q.y; dst[2] = q.z; dst[3] = q.w;
    }
    __syncthreads();

    int lane = threadIdx.x & 31;
    unsigned lt = (1u << lane) - 1u;

    // candidate extraction: each warp-iteration covers (one class, 32 anchors)
    for (int i = threadIdx.x; i < NCLS * 64; i += 512) {
        int c = i >> 6, la = i & 63;
        float v = tile[la * 85 + c];
        bool cand = (la < nA) && (v > LOGIT_T0);
        unsigned m = __ballot_sync(0xFFFFFFFFu, cand);
        if (m) {
            int ldr = __ffs(m) - 1;
            int bs = 0;
            if (lane == ldr) bs = atomicAdd(&g_cand_cnt[b * NCLS + c], __popc(m));
            bs = __shfl_sync(0xFFFFFFFFu, bs, ldr);
            if (cand) {
                int slot = bs + __popc(m & lt);
                if (slot < CAP) {
                    g_cand[(b * NCLS + c) * CAP + slot] =
                        make_uint2(__float_as_uint(sigmoid_f(v)), (unsigned)(a0 + la));
                }
            }
        }
    }

    // decoded boxes (threads 0..63)
    if (threadIdx.x < 64) {
        int la = threadIdx.x;
        if (la < nA) {
            int a = a0 + la;
            int lvl, rem, fw;
            if      (a < 57600) { lvl = 0; rem = a;          fw = 80; }
            else if (a < 72000) { lvl = 1; rem = a - 57600;  fw = 40; }
            else if (a < 75600) { lvl = 2; rem = a - 72000;  fw = 20; }
            else if (a < 76500) { lvl = 3; rem = a - 75600;  fw = 10; }
            else                { lvl = 4; rem = a - 76500;  fw = 5;  }
            int k = rem % 9, cell = rem / 9;
            int x = cell % fw, y = cell / fw;
            float stride = (float)(8 << lvl);
            float acx = ((float)x + 0.5f) * stride;
            float acy = ((float)y + 0.5f) * stride;
            float aw = g_dims[(lvl * 9 + k) * 2 + 0];
            float ah = g_dims[(lvl * 9 + k) * 2 + 1];
            float bp0 = tile[la * 85 + 80] * 0.1f;
            float bp1 = tile[la * 85 + 81] * 0.1f;
            float bp2 = tile[la * 85 + 82] * 0.2f;
            float bp3 = tile[la * 85 + 83] * 0.2f;
            float4 o;
            o.x = bp0 * aw + acx;
            o.y = bp1 * ah + acy;
            o.z = expf(bp2) * aw;
            o.w = expf(bp3) * ah;
            g_boxes[b * A_TOT + a] = o;
        }
    }
}

// ---------------- kernel 2: per-(b,c) top-512 + NMS + per-class top-100 ----------------
__global__ void __launch_bounds__(512) k_nms(const float* __restrict__ pred) {
    __shared__ __align__(16) unsigned int sh_mask[KCAND * 16];  // 32 KB (overlaid scratch)
    __shared__ unsigned long long sh_key[KCAND];                // 4 KB
    __shared__ float sh_c0[KCAND], sh_c1[KCAND], sh_c2[KCAND], sh_c3[KCAND], sh_ar[KCAND];
    __shared__ unsigned int sh_keep[16];
    __shared__ int sh_misc[8];

    int bc = blockIdx.x;
    int b = bc / NCLS, c = bc % NCLS;
    int lane = threadIdx.x & 31;
    unsigned lt = (1u << lane) - 1u;

    int n = g_cand_cnt[bc];

    if (n >= KCAND && n <= CAP) {
        // -------- fast path: sort the <=1024 prefiltered candidates --------
        unsigned long long* buf = (unsigned long long*)sh_mask;   // 1024 u64 = 8 KB
        for (int s = threadIdx.x; s < CAP; s += 512) {
            unsigned long long key = 0ull;
            if (s < n) {
                uint2 r = g_cand[bc * CAP + s];
                key = (((unsigned long long)r.x) << 32) | (unsigned)(~r.y);
            }
            buf[s] = key;
        }
        __syncthreads();
        bitonic_u64_desc(buf, CAP);
        for (int s = threadIdx.x; s < KCAND; s += 512) sh_key[s] = buf[s];
        __syncthreads();
    } else {
        // -------- fallback (statistically never taken; exact & correct) --------
        unsigned int* hist     = sh_mask;
        unsigned int* cand_sc  = sh_mask + 256;
        unsigned int* cand_idx = sh_mask + 768;
        unsigned int* tie_idx  = sh_mask + 1280;
        const float* sbase = pred + (size_t)b * A_TOT * 84 + c;

        int E;
        unsigned T = radix_select_topk(sbase, 84, true, A_TOT, A_PAD, KCAND, hist, sh_misc, &E);
        int G = KCAND - E;

        if (threadIdx.x == 0) { sh_misc[2] = 0; sh_misc[3] = 0; }
        __syncthreads();
        for (int i = threadIdx.x; i < A_PAD; i += 512) {
            unsigned u = 0; bool inb = i < A_TOT;
            if (inb) u = __float_as_uint(sigmoid_f(sbase[(size_t)i * 84]));
            bool gt = inb && (u > T);
            bool eq = inb && (u == T);
            unsigned bg = __ballot_sync(0xFFFFFFFFu, gt);
            if (bg) {
                int ldr = __ffs(bg) - 1; int bs = 0;
                if (lane == ldr && gt) bs = atomicAdd(&sh_misc[2], __popc(bg));
                bs = __shfl_sync(0xFFFFFFFFu, bs, ldr);
                if (gt) {
                    int pos = bs + __popc(bg & lt);
                    if (pos < KCAND) { cand_sc[pos] = u; cand_idx[pos] = (unsigned)i; }
                }
            }
            unsigned be = __ballot_sync(0xFFFFFFFFu, eq);
            if (be) {
                int ldr = __ffs(be) - 1; int bs = 0;
                if (lane == ldr && eq) bs = atomicAdd(&sh_misc[3], __popc(be));
                bs = __shfl_sync(0xFFFFFFFFu, bs, ldr);
                if (eq) {
                    int pos = bs + __popc(be & lt);
                    if (pos < KCAND) tie_idx[pos] = (unsigned)i;
                }
            }
        }
        __syncthreads();
        int nt = sh_misc[3];
        for (int s = threadIdx.x; s < KCAND; s += 512)
            if (s >= nt) tie_idx[s] = 0xFFFFFFFFu;
        __syncthreads();
        bitonic_u32_asc(tie_idx, KCAND);
        for (int s = threadIdx.x; s < KCAND; s += 512) {
            unsigned long long key;
            if (s < G) key = (((unsigned long long)cand_sc[s]) << 32) | (unsigned)(~cand_idx[s]);
            else       key = (((unsigned long long)T) << 32)          | (unsigned)(~tie_idx[s - G]);
            sh_key[s] = key;
        }
        __syncthreads();
        bitonic_u64_desc(sh_key, KCAND);
    }

    // ---- gather boxes ----
    for (int s = threadIdx.x; s < KCAND; s += 512) {
        unsigned idx = ~((unsigned)(sh_key[s] & 0xFFFFFFFFull));
        float4 bx = g_boxes[b * A_TOT + (int)idx];
        sh_c0[s] = bx.x; sh_c1[s] = bx.y; sh_c2[s] = bx.z; sh_c3[s] = bx.w;
        sh_ar[s] = fmaxf(bx.z - bx.x, 0.f) * fmaxf(bx.w - bx.y, 0.f);
    }
    __syncthreads();

    // ---- IoU suppression bitmask (division guarded; identical semantics) ----
    for (int task = threadIdx.x; task < KCAND * 16; task += 512) {
        int w = task >> 9;
        int i = task & 511;
        int j0 = w << 5;
        unsigned bits = 0;
        if (j0 + 31 > i) {
            float iy1 = sh_c0[i], ix1 = sh_c1[i], iy2 = sh_c2[i], ix2 = sh_c3[i], ia = sh_ar[i];
            #pragma unroll 8
            for (int jj = 0; jj < 32; jj++) {
                int j = j0 + jj;
                if (j > i) {
                    float ih = fmaxf(fminf(iy2, sh_c2[j]) - fmaxf(iy1, sh_c0[j]), 0.f);
                    float iw = fmaxf(fminf(ix2, sh_c3[j]) - fmaxf(ix1, sh_c1[j]), 0.f);
                    float inter = ih * iw;
                    if (inter > 0.f) {
                        float un = ia + sh_ar[j] - inter;
                        if (un > 0.f && inter / un > 0.5f) bits |= (1u << jj);
                    }
                }
            }
        }
        sh_mask[i * 16 + w] = bits;
    }
    __syncthreads();

    // ---- greedy NMS: lanes 0..15 hold keep words; mask rows software-pipelined ----
    if (threadIdx.x < 16) {
        unsigned keep = 0;
        for (int t = 0; t < 32; t++) {
            float scf = __uint_as_float((unsigned)(sh_key[threadIdx.x * 32 + t] >> 32));
            if (scf > 0.05f) keep |= (1u << t);
        }
        unsigned m = sh_mask[threadIdx.x];
        for (int i = 0; i < KCAND; i++) {
            unsigned mn = (i + 1 < KCAND) ? sh_mask[(i + 1) * 16 + threadIdx.x] : 0u;
            unsigned kw = __shfl_sync(0x0000FFFFu, keep, i >> 5);
            if ((kw >> (i & 31)) & 1u) keep &= ~m;
            m = mn;
        }
        sh_keep[threadIdx.x] = keep;
    }
    __syncthreads();

    // ---- emit per-class top-100 (kept in score order, then suppressed) ----
    int nk = 0;
    for (int w = 0; w < 16; w++) nk += __popc(sh_keep[w]);
    for (int s = threadIdx.x; s < KCAND; s += 512) {
        int w = s >> 5, bpos = s & 31;
        unsigned kw = sh_keep[w];
        bool kept = (kw >> bpos) & 1u;
        int pre = 0;
        for (int q = 0; q < w; q++) pre += __popc(sh_keep[q]);
        pre += __popc(kw & ((1u << bpos) - 1u));
        int r = kept ? pre : (nk + (s - pre));
        if (r < MAXPC) {
            float scf = __uint_as_float((unsigned)(sh_key[s] >> 32));
            int ob = (b * NCLS + c) * MAXPC + r;
            g_cls_scores[ob] = kept ? scf : 0.0f;
            float4 bx; bx.x = sh_c0[s]; bx.y = sh_c1[s]; bx.z = sh_c2[s]; bx.w = sh_c3[s];
            g_cls_boxes[ob] = bx;
        }
    }
}

// ---------------- kernel 3: combine (per batch), 1024 threads ----------------
__global__ void __launch_bounds__(1024) k_combine(float* __restrict__ out, int out_size) {
    __shared__ unsigned int csh[256 + 128 + 128 + 512];
    __shared__ unsigned long long ckey[128];
    __shared__ int cmisc[8];
    unsigned int* hist     = csh;
    unsigned int* cand_sc  = csh + 256;
    unsigned int* cand_idx = csh + 384;
    unsigned int* tie      = csh + 512;

    int b = blockIdx.x;
    const float* sc = g_cls_scores + b * (NCLS * MAXPC);
    const int N = NCLS * MAXPC;
    const int NP = 8192;

    int lane = threadIdx.x & 31;
    unsigned lt = (1u << lane) - 1u;

    int E;
    unsigned T = radix_select_topk(sc, 1, false, N, NP, MAXPC, hist, cmisc, &E);
    int G = MAXPC - E;

    if (threadIdx.x == 0) { cmisc[2] = 0; cmisc[3] = 0; cmisc[4] = 0; }
    __syncthreads();
    for (int i = threadIdx.x; i < NP; i += 1024) {
        unsigned u = 0; bool inb = i < N;
        if (inb) u = __float_as_uint(sc[i]);
        bool gt = inb && (u > T);
        bool eq = inb && (u == T);
        unsigned bg = __ballot_sync(0xFFFFFFFFu, gt);
        if (bg) {
            int ldr = __ffs(bg) - 1; int bs = 0;
            if (lane == ldr && gt) bs = atomicAdd(&cmisc[2], __popc(bg));
            bs = __shfl_sync(0xFFFFFFFFu, bs, ldr);
            if (gt) {
                int pos = bs + __popc(bg & lt);
                if (pos < 128) { cand_sc[pos] = u; cand_idx[pos] = (unsigned)i; }
            }
        }
        unsigned be = __ballot_sync(0xFFFFFFFFu, eq);
        if (be) {
            int ldr = __ffs(be) - 1; int bs = 0;
            if (lane == ldr && eq) bs = atomicAdd(&cmisc[3], __popc(be));
            bs = __shfl_sync(0xFFFFFFFFu, bs, ldr);
            if (eq) {
                int pos = bs + __popc(be & lt);
                if (pos < 512) tie[pos] = (unsigned)i;
            }
        }
    }
    __syncthreads();
    int nt = cmisc[3];
    for (int s = threadIdx.x; s < 512; s += 1024)
        if (s >= nt) tie[s] = 0xFFFFFFFFu;
    __syncthreads();
    bitonic_u32_asc(tie, 512);

    for (int s = threadIdx.x; s < 128; s += 1024) {
        unsigned long long key;
        if (s < G)           key = (((unsigned long long)cand_sc[s]) << 32) | (unsigned)(~cand_idx[s]);
        else if (s < MAXPC)  key = (((unsigned long long)T) << 32)          | (unsigned)(~tie[s - G]);
        else                 key = 0ull;
        ckey[s] = key;
    }
    __syncthreads();
    bitonic_u64_desc(ckey, 128);

    int r = threadIdx.x;
    if (r < MAXPC) {
        unsigned long long kk = ckey[r];
        float s = __uint_as_float((unsigned)(kk >> 32));
        bool valid = s > 0.0f;
        float b0 = 0.f, b1 = 0.f, b2 = 0.f, b3 = 0.f, cls = 0.f, so = 0.f;
        if (valid) {
            unsigned f = ~((unsigned)(kk & 0xFFFFFFFFull));
            int ci = (int)f / MAXPC;
            float4 bb = g_cls_boxes[b * N + (int)f];
            b0 = fminf(fmaxf(bb.x, 0.f), 1.f);
            b1 = fminf(fmaxf(bb.y, 0.f), 1.f);
            b2 = fminf(fmaxf(bb.z, 0.f), 1.f);
            b3 = fminf(fmaxf(bb.w, 0.f), 1.f);
            cls = (float)ci;
            so = s;
            atomicAdd(&cmisc[4], 1);
        }
        int ob = (b * MAXPC + r) * 4;
        if (ob + 3 < out_size) {
            out[ob + 0] = b0; out[ob + 1] = b1; out[ob + 2] = b2; out[ob + 3] = b3;
        }
        int os = BATCH * MAXPC * 4 + b * MAXPC + r;
        if (os < out_size) out[os] = so;
        int oc = BATCH * MAXPC * 4 + BATCH * MAXPC + b * MAXPC + r;
        if (oc < out_size) out[oc] = cls;
    }
    __syncthreads();
    if (threadIdx.x == 0) {
        int ov = BATCH * MAXPC * 4 + 2 * BATCH * MAXPC + b;
        if (ov < out_size) out[ov] = (float)cmisc[4];
    }
}

// ---------------- launch ----------------
extern "C" void kernel_launch(void* const* d_in, const int* in_sizes, int n_in,
                              void* d_out, int out_size) {
    const float* pred;
    if (n_in >= 2 && in_sizes[0] == BATCH * A_TOT * 84) pred = (const float*)d_in[0];
    else                                                pred = (const float*)d_in[1];
    float* out = (float*)d_out;

    k_init<<<1, 512>>>();
    k_decode<<<dim3((A_TOT + 63) / 64, BATCH), 512>>>(pred);
    k_nms<<<BATCH * NCLS, 512>>>(pred);
    k_combine<<<BATCH, 1024>>>(out, out_size);
}

// round 8
// speedup vs baseline: 5.9641x; 1.6317x over previous
#include <cuda_runtime.h>
#include <cstdint>

#define BATCH 4
#define A_TOT 76725
#define A_PAD 76800
#define NCLS  80
#define KCAND 512
#define MAXPC 100
#define CAP   1024
// logit(0.91) = ln(0.91/0.09)
#define LOGIT_T0 2.3136349f

// ---------------- scratch (device globals; statically zero-initialized) ----------------
__device__ float4 g_boxes[BATCH * A_TOT];                     // decoded [x,y,w,h]
__device__ uint2  g_cand[BATCH * NCLS * CAP];                 // (score_bits, anchor_idx)
__device__ int    g_cand_cnt[BATCH * NCLS];                   // zero-init; k_nms resets after use
__device__ float  g_cls_scores[BATCH * NCLS * MAXPC];
__device__ float4 g_cls_boxes[BATCH * NCLS * MAXPC];

// ---------------- helpers ----------------
__device__ __forceinline__ float sigmoid_f(float x) {
    if (x >= 0.f) { float z = expf(-x); return 1.f / (1.f + z); }
    float z = expf(x); return z / (1.f + z);
}

__device__ void bitonic_u64_desc(unsigned long long* key, int n) {
    for (int k = 2; k <= n; k <<= 1) {
        for (int j = k >> 1; j > 0; j >>= 1) {
            for (int idx = threadIdx.x; idx < n; idx += blockDim.x) {
                int p = idx ^ j;
                if (p > idx) {
                    unsigned long long a = key[idx], b = key[p];
                    bool up = ((idx & k) == 0);
                    bool sw = up ? (a < b) : (a > b);
                    if (sw) { key[idx] = b; key[p] = a; }
                }
            }
            __syncthreads();
        }
    }
}

__device__ void bitonic_u32_asc(unsigned int* key, int n) {
    for (int k = 2; k <= n; k <<= 1) {
        for (int j = k >> 1; j > 0; j >>= 1) {
            for (int idx = threadIdx.x; idx < n; idx += blockDim.x) {
                int p = idx ^ j;
                if (p > idx) {
                    unsigned int a = key[idx], b = key[p];
                    bool up = ((idx & k) == 0);
                    bool sw = up ? (a > b) : (a < b);
                    if (sw) { key[idx] = b; key[p] = a; }
                }
            }
            __syncthreads();
        }
    }
}

// warp-parallel "pick threshold bucket" over a 256-bin shared histogram.
__device__ __forceinline__ void pick_bucket(unsigned* hist, int* misc, int K) {
    if (threadIdx.x < 32) {
        int l = threadIdx.x;
        int base = 255 - l * 8;
        unsigned hv[8]; unsigned t = 0;
        #pragma unroll
        for (int q = 0; q < 8; q++) { hv[q] = hist[base - q]; t += hv[q]; }
        unsigned p = t;
        #pragma unroll
        for (int o = 1; o < 32; o <<= 1) {
            unsigned v = __shfl_up_sync(0xFFFFFFFFu, p, o);
            if (l >= o) p += v;
        }
        unsigned excl = p - t;
        bool has = (excl < (unsigned)K) && ((unsigned)K <= excl + t);
        unsigned bal = __ballot_sync(0xFFFFFFFFu, has);
        int ldr = __ffs(bal) - 1;
        if (l == ldr) {
            unsigned cum = excl; int chosen = base;
            #pragma unroll
            for (int q = 0; q < 8; q++) {
                if (cum + hv[q] >= (unsigned)K) { chosen = base - q; break; }
                cum += hv[q];
            }
            misc[0] = chosen; misc[1] = (int)cum;
        }
    }
    __syncthreads();
}

// 4-pass radix select; returns bits of K-th largest; *E_out = #ties in top-K.
__device__ unsigned radix_select_topk(const float* base, int stride, bool sig,
                                      int N, int Npad, int K,
                                      unsigned* hist, int* misc, int* E_out) {
    unsigned prefix = 0;
    int lane = threadIdx.x & 31;
    unsigned lt = (1u << lane) - 1u;
    for (int pass = 0; pass < 4; pass++) {
        int shift = 24 - 8 * pass;
        for (int i = threadIdx.x; i < 256; i += blockDim.x) hist[i] = 0;
        __syncthreads();
        unsigned himask = pass ? (0xFFFFFFFFu << (shift + 8)) : 0u;
        for (int i = threadIdx.x; i < Npad; i += blockDim.x) {
            unsigned u = 0; bool ok = false;
            if (i < N) {
                float v = base[(size_t)i * stride];
                if (sig) v = sigmoid_f(v);
                u = __float_as_uint(v);
                ok = (pass == 0) || ((u & himask) == prefix);
            }
            unsigned bk = ok ? ((u >> shift) & 0xFFu) : (0x200u + (unsigned)lane);
            unsigned peers = __match_any_sync(0xFFFFFFFFu, bk);
            if (ok && ((peers & lt) == 0u)) atomicAdd(&hist[bk], (unsigned)__popc(peers));
        }
        __syncthreads();
        pick_bucket(hist, misc, K);
        K -= misc[1];
        prefix |= ((unsigned)misc[0]) << shift;
        __syncthreads();
    }
    *E_out = K;
    return prefix;
}

// ---------------- kernel 1: decode boxes + candidate extraction (64 anchors/block) ----------------
__global__ void __launch_bounds__(512) k_decode(const float* __restrict__ pred) {
    __shared__ float tile[64 * 85];
    int b = blockIdx.y;
    int a0 = blockIdx.x * 64;
    int nA = min(64, A_TOT - a0);
    const float* base = pred + ((size_t)b * A_TOT + a0) * 84;
    int cnt4 = (nA * 84) >> 2;
    const float4* base4 = (const float4*)base;
    for (int v = threadIdx.x; v < cnt4; v += 512) {
        float4 q = base4[v];
        int i0 = v * 4;
        int la = i0 / 84, ch = i0 - la * 84;
        float* dst = &tile[la * 85 + ch];
        dst[0] = q.x; dst[1] = q.y; dst[2] = q.z; dst[3] = q.w;
    }
    __syncthreads();

    int lane = threadIdx.x & 31;
    unsigned lt = (1u << lane) - 1u;

    for (int i = threadIdx.x; i < NCLS * 64; i += 512) {
        int c = i >> 6, la = i & 63;
        float v = tile[la * 85 + c];
        bool cand = (la < nA) && (v > LOGIT_T0);
        unsigned m = __ballot_sync(0xFFFFFFFFu, cand);
        if (m) {
            int ldr = __ffs(m) - 1;
            int bs = 0;
            if (lane == ldr) bs = atomicAdd(&g_cand_cnt[b * NCLS + c], __popc(m));
            bs = __shfl_sync(0xFFFFFFFFu, bs, ldr);
            if (cand) {
                int slot = bs + __popc(m & lt);
                if (slot < CAP) {
                    g_cand[(b * NCLS + c) * CAP + slot] =
                        make_uint2(__float_as_uint(sigmoid_f(v)), (unsigned)(a0 + la));
                }
            }
        }
    }

    // decoded boxes (threads 0..63); anchor dims computed inline in double (matches numpy)
    if (threadIdx.x < 64) {
        int la = threadIdx.x;
        if (la < nA) {
            int a = a0 + la;
            int lvl, rem, fw;
            if      (a < 57600) { lvl = 0; rem = a;          fw = 80; }
            else if (a < 72000) { lvl = 1; rem = a - 57600;  fw = 40; }
            else if (a < 75600) { lvl = 2; rem = a - 72000;  fw = 20; }
            else if (a < 76500) { lvl = 3; rem = a - 75600;  fw = 10; }
            else                { lvl = 4; rem = a - 76500;  fw = 5;  }
            int k = rem % 9, cell = rem / 9;
            int x = cell % fw, y = cell / fw;
            int ri = k / 3, si = k % 3;
            double r  = (ri == 0) ? 0.5 : (ri == 1 ? 1.0 : 2.0);
            double sv = (si == 0) ? 1.0
                      : (si == 1 ? 1.2599210498948731647672106072782
                                 : 1.5874010519681994747517056392723);
            double side = (double)(1 << (lvl + 5));
            double area = side * side;
            double ahd = sqrt(area / r);
            double awd = area / ahd;
            float aw = (float)(sv * awd);
            float ah = (float)(sv * ahd);
            float stride = (float)(8 << lvl);
            float acx = ((float)x + 0.5f) * stride;
            float acy = ((float)y + 0.5f) * stride;
            float bp0 = tile[la * 85 + 80] * 0.1f;
            float bp1 = tile[la * 85 + 81] * 0.1f;
            float bp2 = tile[la * 85 + 82] * 0.2f;
            float bp3 = tile[la * 85 + 83] * 0.2f;
            float4 o;
            o.x = bp0 * aw + acx;
            o.y = bp1 * ah + acy;
            o.z = expf(bp2) * aw;
            o.w = expf(bp3) * ah;
            g_boxes[b * A_TOT + a] = o;
        }
    }
}

// ---------------- kernel 2: per-(b,c) top-512 + NMS + per-class top-100 ----------------
__global__ void __launch_bounds__(512) k_nms(const float* __restrict__ pred) {
    __shared__ __align__(16) unsigned int sh_mask[KCAND * 16];  // 32 KB (overlaid scratch)
    __shared__ unsigned long long sh_key[KCAND];                // 4 KB
    __shared__ __align__(16) float4 sh_box[KCAND];              // 8 KB
    __shared__ float sh_ar[KCAND];                              // 2 KB
    __shared__ unsigned int sh_keep[16];
    __shared__ int sh_misc[8];

    int bc = blockIdx.x;
    int b = bc / NCLS, c = bc % NCLS;
    int lane = threadIdx.x & 31;
    unsigned lt = (1u << lane) - 1u;

    int n = g_cand_cnt[bc];

    if (n >= KCAND && n <= CAP) {
        // -------- fast path: sort the <=1024 prefiltered candidates --------
        unsigned long long* buf = (unsigned long long*)sh_mask;   // 1024 u64 = 8 KB
        for (int s = threadIdx.x; s < CAP; s += 512) {
            unsigned long long key = 0ull;
            if (s < n) {
                uint2 r = g_cand[bc * CAP + s];
                key = (((unsigned long long)r.x) << 32) | (unsigned)(~r.y);
            }
            buf[s] = key;
        }
        __syncthreads();
        bitonic_u64_desc(buf, CAP);
        for (int s = threadIdx.x; s < KCAND; s += 512) sh_key[s] = buf[s];
        __syncthreads();
    } else {
        // -------- fallback (statistically never taken; exact & correct) --------
        unsigned int* hist     = sh_mask;
        unsigned int* cand_sc  = sh_mask + 256;
        unsigned int* cand_idx = sh_mask + 768;
        unsigned int* tie_idx  = sh_mask + 1280;
        const float* sbase = pred + (size_t)b * A_TOT * 84 + c;

        int E;
        unsigned T = radix_select_topk(sbase, 84, true, A_TOT, A_PAD, KCAND, hist, sh_misc, &E);
        int G = KCAND - E;

        if (threadIdx.x == 0) { sh_misc[2] = 0; sh_misc[3] = 0; }
        __syncthreads();
        for (int i = threadIdx.x; i < A_PAD; i += 512) {
            unsigned u = 0; bool inb = i < A_TOT;
            if (inb) u = __float_as_uint(sigmoid_f(sbase[(size_t)i * 84]));
            bool gt = inb && (u > T);
            bool eq = inb && (u == T);
            unsigned bg = __ballot_sync(0xFFFFFFFFu, gt);
            if (bg) {
                int ldr = __ffs(bg) - 1; int bs = 0;
                if (lane == ldr && gt) bs = atomicAdd(&sh_misc[2], __popc(bg));
                bs = __shfl_sync(0xFFFFFFFFu, bs, ldr);
                if (gt) {
                    int pos = bs + __popc(bg & lt);
                    if (pos < KCAND) { cand_sc[pos] = u; cand_idx[pos] = (unsigned)i; }
                }
            }
            unsigned be = __ballot_sync(0xFFFFFFFFu, eq);
            if (be) {
                int ldr = __ffs(be) - 1; int bs = 0;
                if (lane == ldr && eq) bs = atomicAdd(&sh_misc[3], __popc(be));
                bs = __shfl_sync(0xFFFFFFFFu, bs, ldr);
                if (eq) {
                    int pos = bs + __popc(be & lt);
                    if (pos < KCAND) tie_idx[pos] = (unsigned)i;
                }
            }
        }
        __syncthreads();
        int nt = sh_misc[3];
        for (int s = threadIdx.x; s < KCAND; s += 512)
            if (s >= nt) tie_idx[s] = 0xFFFFFFFFu;
        __syncthreads();
        bitonic_u32_asc(tie_idx, KCAND);
        for (int s = threadIdx.x; s < KCAND; s += 512) {
            unsigned long long key;
            if (s < G) key = (((unsigned long long)cand_sc[s]) << 32) | (unsigned)(~cand_idx[s]);
            else       key = (((unsigned long long)T) << 32)          | (unsigned)(~tie_idx[s - G]);
            sh_key[s] = key;
        }
        __syncthreads();
        bitonic_u64_desc(sh_key, KCAND);
    }

    // ---- gather boxes (float4 + area) ----
    for (int s = threadIdx.x; s < KCAND; s += 512) {
        unsigned idx = ~((unsigned)(sh_key[s] & 0xFFFFFFFFull));
        float4 bx = g_boxes[b * A_TOT + (int)idx];
        sh_box[s] = bx;
        sh_ar[s] = fmaxf(bx.z - bx.x, 0.f) * fmaxf(bx.w - bx.y, 0.f);
    }
    __syncthreads();

    // ---- IoU suppression bitmask (2 LDS per j: float4 + area) ----
    for (int task = threadIdx.x; task < KCAND * 16; task += 512) {
        int w = task >> 9;
        int i = task & 511;
        int j0 = w << 5;
        unsigned bits = 0;
        if (j0 + 31 > i) {
            float4 bi = sh_box[i]; float ia = sh_ar[i];
            #pragma unroll 8
            for (int jj = 0; jj < 32; jj++) {
                int j = j0 + jj;
                if (j > i) {
                    float4 bj = sh_box[j];
                    float ih = fmaxf(fminf(bi.z, bj.z) - fmaxf(bi.x, bj.x), 0.f);
                    float iw = fmaxf(fminf(bi.w, bj.w) - fmaxf(bi.y, bj.y), 0.f);
                    float inter = ih * iw;
                    if (inter > 0.f) {
                        float un = ia + sh_ar[j] - inter;
                        if (un > 0.f && inter / un > 0.5f) bits |= (1u << jj);
                    }
                }
            }
        }
        sh_mask[i * 16 + w] = bits;
    }
    __syncthreads();

    // ---- blocked greedy NMS: word-serial in registers + parallel cross-word apply ----
    // Equivalent to: for i asc: if keep[i]: keep &= ~mask[i]  (mask strictly upper-triangular)
    if (threadIdx.x < 16) {
        int l = threadIdx.x;
        unsigned keep = 0;
        #pragma unroll
        for (int t = 0; t < 32; t++) {
            float scf = __uint_as_float((unsigned)(sh_key[l * 32 + t] >> 32));
            if (scf > 0.05f) keep |= (1u << t);
        }
        for (int w0 = 0; w0 < 16; w0++) {
            if (l == w0) {
                // serial within-word resolution (exact visit order), 8-reg chunks
                #pragma unroll
                for (int ch = 0; ch < 4; ch++) {
                    unsigned m[8];
                    #pragma unroll
                    for (int t = 0; t < 8; t++)
                        m[t] = sh_mask[(w0 * 32 + ch * 8 + t) * 16 + w0];
                    #pragma unroll
                    for (int t = 0; t < 8; t++) {
                        int bit = ch * 8 + t;
                        if ((keep >> bit) & 1u) keep &= ~m[t];
                    }
                }
            }
            unsigned kw = __shfl_sync(0xFFFFu, keep, w0);
            // all lanes: apply suppression from word-w0's final kept set
            unsigned acc = 0;
            #pragma unroll
            for (int ch = 0; ch < 4; ch++) {
                unsigned m[8];
                #pragma unroll
                for (int t = 0; t < 8; t++)
                    m[t] = sh_mask[(w0 * 32 + ch * 8 + t) * 16 + l];
                #pragma unroll
                for (int t = 0; t < 8; t++)
                    acc |= m[t] & (0u - ((kw >> (ch * 8 + t)) & 1u));
            }
            keep &= ~acc;
        }
        sh_keep[l] = keep;
    }
    __syncthreads();

    // ---- emit per-class top-100 (kept in score order, then suppressed) ----
    int nk = 0;
    for (int w = 0; w < 16; w++) nk += __popc(sh_keep[w]);
    for (int s = threadIdx.x; s < KCAND; s += 512) {
        int w = s >> 5, bpos = s & 31;
        unsigned kw = sh_keep[w];
        bool kept = (kw >> bpos) & 1u;
        int pre = 0;
        for (int q = 0; q < w; q++) pre += __popc(sh_keep[q]);
        pre += __popc(kw & ((1u << bpos) - 1u));
        int r = kept ? pre : (nk + (s - pre));
        if (r < MAXPC) {
            float scf = __uint_as_float((unsigned)(sh_key[s] >> 32));
            int ob = (b * NCLS + c) * MAXPC + r;
            g_cls_scores[ob] = kept ? scf : 0.0f;
            g_cls_boxes[ob] = sh_box[s];
        }
    }

    // reset counter for next replay (every thread read n before the first barrier)
    if (threadIdx.x == 0) g_cand_cnt[bc] = 0;
}

// ---------------- kernel 3: combine (per batch), 1024 threads ----------------
__global__ void __launch_bounds__(1024) k_combine(float* __restrict__ out, int out_size) {
    __shared__ unsigned int csh[256 + 128 + 128 + 512];
    __shared__ unsigned int tsort[512];
    __shared__ unsigned long long ckey[128];
    __shared__ int cmisc[8];
    unsigned int* hist     = csh;
    unsigned int* cand_sc  = csh + 256;
    unsigned int* cand_idx = csh + 384;
    unsigned int* tie      = csh + 512;

    int b = blockIdx.x;
    const float* sc = g_cls_scores + b * (NCLS * MAXPC);
    const int N = NCLS * MAXPC;
    const int NP = 8192;

    int lane = threadIdx.x & 31;
    unsigned lt = (1u << lane) - 1u;

    int E;
    unsigned T = radix_select_topk(sc, 1, false, N, NP, MAXPC, hist, cmisc, &E);
    int G = MAXPC - E;

    if (threadIdx.x == 0) { cmisc[2] = 0; cmisc[3] = 0; cmisc[4] = 0; }
    __syncthreads();
    for (int i = threadIdx.x; i < NP; i += 1024) {
        unsigned u = 0; bool inb = i < N;
        if (inb) u = __float_as_uint(sc[i]);
        bool gt = inb && (u > T);
        bool eq = inb && (u == T);
        unsigned bg = __ballot_sync(0xFFFFFFFFu, gt);
        if (bg) {
            int ldr = __ffs(bg) - 1; int bs = 0;
            if (lane == ldr && gt) bs = atomicAdd(&cmisc[2], __popc(bg));
            bs = __shfl_sync(0xFFFFFFFFu, bs, ldr);
            if (gt) {
                int pos = bs + __popc(bg & lt);
                if (pos < 128) { cand_sc[pos] = u; cand_idx[pos] = (unsigned)i; }
            }
        }
        unsigned be = __ballot_sync(0xFFFFFFFFu, eq);
        if (be) {
            int ldr = __ffs(be) - 1; int bs = 0;
            if (lane == ldr && eq) bs = atomicAdd(&cmisc[3], __popc(be));
            bs = __shfl_sync(0xFFFFFFFFu, bs, ldr);
            if (eq) {
                int pos = bs + __popc(be & lt);
                if (pos < 512) tie[pos] = (unsigned)i;
            }
        }
    }
    __syncthreads();
    int nt = min(cmisc[3], 512);
    // rank-sort the nt tie indices ascending (distinct values => unique ranks)
    for (int s = threadIdx.x; s < nt; s += 1024) {
        unsigned v = tie[s];
        int rk = 0;
        for (int q = 0; q < nt; q++) rk += (tie[q] < v);
        tsort[rk] = v;
    }
    __syncthreads();

    for (int s = threadIdx.x; s < 128; s += 1024) {
        unsigned long long key;
        if (s < G)           key = (((unsigned long long)cand_sc[s]) << 32) | (unsigned)(~cand_idx[s]);
        else if (s < MAXPC)  key = (((unsigned long long)T) << 32)          | (unsigned)(~tsort[s - G]);
        else                 key = 0ull;
        ckey[s] = key;
    }
    __syncthreads();
    bitonic_u64_desc(ckey, 128);

    int r = threadIdx.x;
    if (r < MAXPC) {
        unsigned long long kk = ckey[r];
        float s = __uint_as_float((unsigned)(kk >> 32));
        bool valid = s > 0.0f;
        float b0 = 0.f, b1 = 0.f, b2 = 0.f, b3 = 0.f, cls = 0.f, so = 0.f;
        if (valid) {
            unsigned f = ~((unsigned)(kk & 0xFFFFFFFFull));
            int ci = (int)f / MAXPC;
            float4 bb = g_cls_boxes[b * N + (int)f];
            b0 = fminf(fmaxf(bb.x, 0.f), 1.f);
            b1 = fminf(fmaxf(bb.y, 0.f), 1.f);
            b2 = fminf(fmaxf(bb.z, 0.f), 1.f);
            b3 = fminf(fmaxf(bb.w, 0.f), 1.f);
            cls = (float)ci;
            so = s;
            atomicAdd(&cmisc[4], 1);
        }
        int ob = (b * MAXPC + r) * 4;
        if (ob + 3 < out_size) {
            out[ob + 0] = b0; out[ob + 1] = b1; out[ob + 2] = b2; out[ob + 3] = b3;
        }
        int os = BATCH * MAXPC * 4 + b * MAXPC + r;
        if (os < out_size) out[os] = so;
        int oc = BATCH * MAXPC * 4 + BATCH * MAXPC + b * MAXPC + r;
        if (oc < out_size) out[oc] = cls;
    }
    __syncthreads();
    if (threadIdx.x == 0) {
        int ov = BATCH * MAXPC * 4 + 2 * BATCH * MAXPC + b;
        if (ov < out_size) out[ov] = (float)cmisc[4];
    }
}

// ---------------- launch ----------------
extern "C" void kernel_launch(void* const* d_in, const int* in_sizes, int n_in,
                              void* d_out, int out_size) {
    const float* pred;
    if (n_in >= 2 && in_sizes[0] == BATCH * A_TOT * 84) pred = (const float*)d_in[0];
    else                                                pred = (const float*)d_in[1];
    float* out = (float*)d_out;

    k_decode<<<dim3((A_TOT + 63) / 64, BATCH), 512>>>(pred);
    k_nms<<<BATCH * NCLS, 512>>>(pred);
    k_combine<<<BATCH, 1024>>>(out, out_size);
}

// round 10
// speedup vs baseline: 6.0218x; 1.0097x over previous
#include <cuda_runtime.h>
#include <cstdint>

#define BATCH 4
#define A_TOT 76725
#define A_PAD 76800
#define NCLS  80
#define KCAND 512
#define MAXPC 100
#define CAP   1024
// logit(0.91) = ln(0.91/0.09)
#define LOGIT_T0 2.3136349f

// ---------------- scratch (device globals; statically zero-initialized) ----------------
__device__ float4 g_boxes[BATCH * A_TOT];                     // decoded [x,y,w,h]
__device__ uint2  g_cand[BATCH * NCLS * CAP];                 // (score_bits, anchor_idx)
__device__ int    g_cand_cnt[BATCH * NCLS];                   // zero-init; k_nms resets after use
__device__ float  g_cls_scores[BATCH * NCLS * MAXPC];
__device__ float4 g_cls_boxes[BATCH * NCLS * MAXPC];
__device__ float  g_dims[45 * 2];                             // per (level,k): w,h

// ---------------- helpers ----------------
__device__ __forceinline__ float sigmoid_f(float x) {
    if (x >= 0.f) { float z = expf(-x); return 1.f / (1.f + z); }
    float z = expf(x); return z / (1.f + z);
}

__device__ void bitonic_u64_desc(unsigned long long* key, int n) {
    for (int k = 2; k <= n; k <<= 1) {
        for (int j = k >> 1; j > 0; j >>= 1) {
            for (int idx = threadIdx.x; idx < n; idx += blockDim.x) {
                int p = idx ^ j;
                if (p > idx) {
                    unsigned long long a = key[idx], b = key[p];
                    bool up = ((idx & k) == 0);
                    bool sw = up ? (a < b) : (a > b);
                    if (sw) { key[idx] = b; key[p] = a; }
                }
            }
            __syncthreads();
        }
    }
}

__device__ void bitonic_u32_asc(unsigned int* key, int n) {
    for (int k = 2; k <= n; k <<= 1) {
        for (int j = k >> 1; j > 0; j >>= 1) {
            for (int idx = threadIdx.x; idx < n; idx += blockDim.x) {
                int p = idx ^ j;
                if (p > idx) {
                    unsigned int a = key[idx], b = key[p];
                    bool up = ((idx & k) == 0);
                    bool sw = up ? (a > b) : (a < b);
                    if (sw) { key[idx] = b; key[p] = a; }
                }
            }
            __syncthreads();
        }
    }
}

// warp-parallel "pick threshold bucket" over a 256-bin shared histogram.
__device__ __forceinline__ void pick_bucket(unsigned* hist, int* misc, int K) {
    if (threadIdx.x < 32) {
        int l = threadIdx.x;
        int base = 255 - l * 8;
        unsigned hv[8]; unsigned t = 0;
        #pragma unroll
        for (int q = 0; q < 8; q++) { hv[q] = hist[base - q]; t += hv[q]; }
        unsigned p = t;
        #pragma unroll
        for (int o = 1; o < 32; o <<= 1) {
            unsigned v = __shfl_up_sync(0xFFFFFFFFu, p, o);
            if (l >= o) p += v;
        }
        unsigned excl = p - t;
        bool has = (excl < (unsigned)K) && ((unsigned)K <= excl + t);
        unsigned bal = __ballot_sync(0xFFFFFFFFu, has);
        int ldr = __ffs(bal) - 1;
        if (l == ldr) {
            unsigned cum = excl; int chosen = base;
            #pragma unroll
            for (int q = 0; q < 8; q++) {
                if (cum + hv[q] >= (unsigned)K) { chosen = base - q; break; }
                cum += hv[q];
            }
            misc[0] = chosen; misc[1] = (int)cum;
        }
    }
    __syncthreads();
}

// 4-pass radix select; returns bits of K-th largest; *E_out = #ties in top-K.
__device__ unsigned radix_select_topk(const float* base, int stride, bool sig,
                                      int N, int Npad, int K,
                                      unsigned* hist, int* misc, int* E_out) {
    unsigned prefix = 0;
    int lane = threadIdx.x & 31;
    unsigned lt = (1u << lane) - 1u;
    for (int pass = 0; pass < 4; pass++) {
        int shift = 24 - 8 * pass;
        for (int i = threadIdx.x; i < 256; i += blockDim.x) hist[i] = 0;
        __syncthreads();
        unsigned himask = pass ? (0xFFFFFFFFu << (shift + 8)) : 0u;
        for (int i = threadIdx.x; i < Npad; i += blockDim.x) {
            unsigned u = 0; bool ok = false;
            if (i < N) {
                float v = base[(size_t)i * stride];
                if (sig) v = sigmoid_f(v);
                u = __float_as_uint(v);
                ok = (pass == 0) || ((u & himask) == prefix);
            }
            unsigned bk = ok ? ((u >> shift) & 0xFFu) : (0x200u + (unsigned)lane);
            unsigned peers = __match_any_sync(0xFFFFFFFFu, bk);
            if (ok && ((peers & lt) == 0u)) atomicAdd(&hist[bk], (unsigned)__popc(peers));
        }
        __syncthreads();
        pick_bucket(hist, misc, K);
        K -= misc[1];
        prefix |= ((unsigned)misc[0]) << shift;
        __syncthreads();
    }
    *E_out = K;
    return prefix;
}

// ---------------- kernel 0: anchor dims table (double precision, matches numpy) ----------------
__global__ void k_dims() {
    int t = threadIdx.x;
    if (t < 45) {
        int lvl = t / 9, k = t % 9;
        int ri = k / 3, si = k % 3;
        double r = (ri == 0) ? 0.5 : (ri == 1 ? 1.0 : 2.0);
        double s = pow(2.0, (double)si / 3.0);
        double side = (double)(1 << (lvl + 5));       // 2^(level+2), level = lvl+3
        double area = side * side;
        double ah = sqrt(area / r);
        double aw = area / ah;
        g_dims[t * 2 + 0] = (float)(s * aw);
        g_dims[t * 2 + 1] = (float)(s * ah);
    }
}

// ---------------- kernel 1: streaming decode + candidate extraction (no smem) ----------------
// 84 floats/anchor = 21 float4 chunks; chunk 20 holds the 4 box regressors.
#define NCHUNK (BATCH * A_TOT * 21)

__global__ void __launch_bounds__(512) k_decode(const float4* __restrict__ pred4) {
    int S = gridDim.x * blockDim.x;
    int tid = blockIdx.x * blockDim.x + threadIdx.x;

    for (int base = tid; base < NCHUNK; base += 4 * S) {
        float4 v[4]; int g[4]; bool ok[4];
        #pragma unroll
        for (int t = 0; t < 4; t++) {
            g[t] = base + t * S;
            ok[t] = g[t] < NCHUNK;
            if (ok[t]) v[t] = pred4[g[t]];
        }
        #pragma unroll
        for (int t = 0; t < 4; t++) {
            if (!ok[t]) continue;
            int ag  = g[t] / 21;            // b*A_TOT + a
            int ch4 = g[t] - ag * 21;
            if (ch4 < 20) {
                // 4 class scores, classes c = ch4*4 .. ch4*4+3
                float mx = fmaxf(fmaxf(v[t].x, v[t].y), fmaxf(v[t].z, v[t].w));
                if (mx > LOGIT_T0) {
                    int b = ag / A_TOT;
                    unsigned a = (unsigned)(ag - b * A_TOT);
                    float sv[4] = {v[t].x, v[t].y, v[t].z, v[t].w};
                    #pragma unroll
                    for (int j = 0; j < 4; j++) {
                        if (sv[j] > LOGIT_T0) {
                            int c = ch4 * 4 + j;
                            int slot = atomicAdd(&g_cand_cnt[b * NCLS + c], 1);
                            if (slot < CAP)
                                g_cand[(b * NCLS + c) * CAP + slot] =
                                    make_uint2(__float_as_uint(sigmoid_f(sv[j])), a);
                        }
                    }
                }
            } else {
                // box chunk: decode anchor ag
                int b = ag / A_TOT;
                int a = ag - b * A_TOT;
                int lvl, rem, fw;
                if      (a < 57600) { lvl = 0; rem = a;          fw = 80; }
                else if (a < 72000) { lvl = 1; rem = a - 57600;  fw = 40; }
                else if (a < 75600) { lvl = 2; rem = a - 72000;  fw = 20; }
                else if (a < 76500) { lvl = 3; rem = a - 75600;  fw = 10; }
                else                { lvl = 4; rem = a - 76500;  fw = 5;  }
                int k = rem % 9, cell = rem / 9;
                int x = cell % fw, y = cell / fw;
                float aw = g_dims[(lvl * 9 + k) * 2 + 0];
                float ah = g_dims[(lvl * 9 + k) * 2 + 1];
                float stride = (float)(8 << lvl);
                float acx = ((float)x + 0.5f) * stride;
                float acy = ((float)y + 0.5f) * stride;
                float bp0 = v[t].x * 0.1f;
                float bp1 = v[t].y * 0.1f;
                float bp2 = v[t].z * 0.2f;
                float bp3 = v[t].w * 0.2f;
                float4 o;
                o.x = bp0 * aw + acx;
                o.y = bp1 * ah + acy;
                o.z = expf(bp2) * aw;
                o.w = expf(bp3) * ah;
                g_boxes[ag] = o;
            }
        }
    }
}

// ---------------- kernel 2: per-(b,c) top-512 + NMS + per-class top-100 ----------------
__global__ void __launch_bounds__(512) k_nms(const float* __restrict__ pred) {
    __shared__ __align__(16) unsigned int sh_mask[KCAND * 16];  // 32 KB (overlaid scratch)
    __shared__ unsigned long long sh_key[KCAND];                // 4 KB
    __shared__ __align__(16) float4 sh_box[KCAND];              // 8 KB
    __shared__ float sh_ar[KCAND];                              // 2 KB
    __shared__ unsigned int sh_keep[16];
    __shared__ int sh_misc[8];

    int bc = blockIdx.x;
    int b = bc / NCLS, c = bc % NCLS;
    int lane = threadIdx.x & 31;
    unsigned lt = (1u << lane) - 1u;

    int n = g_cand_cnt[bc];

    if (n >= KCAND && n <= CAP) {
        // -------- fast path: sort the <=1024 prefiltered candidates --------
        unsigned long long* buf = (unsigned long long*)sh_mask;   // 1024 u64 = 8 KB
        for (int s = threadIdx.x; s < CAP; s += 512) {
            unsigned long long key = 0ull;
            if (s < n) {
                uint2 r = g_cand[bc * CAP + s];
                key = (((unsigned long long)r.x) << 32) | (unsigned)(~r.y);
            }
            buf[s] = key;
        }
        __syncthreads();
        bitonic_u64_desc(buf, CAP);
        for (int s = threadIdx.x; s < KCAND; s += 512) sh_key[s] = buf[s];
        __syncthreads();
    } else {
        // -------- fallback (statistically never taken; exact & correct) --------
        unsigned int* hist     = sh_mask;
        unsigned int* cand_sc  = sh_mask + 256;
        unsigned int* cand_idx = sh_mask + 768;
        unsigned int* tie_idx  = sh_mask + 1280;
        const float* sbase = pred + (size_t)b * A_TOT * 84 + c;

        int E;
        unsigned T = radix_select_topk(sbase, 84, true, A_TOT, A_PAD, KCAND, hist, sh_misc, &E);
        int G = KCAND - E;

        if (threadIdx.x == 0) { sh_misc[2] = 0; sh_misc[3] = 0; }
        __syncthreads();
        for (int i = threadIdx.x; i < A_PAD; i += 512) {
            unsigned u = 0; bool inb = i < A_TOT;
            if (inb) u = __float_as_uint(sigmoid_f(sbase[(size_t)i * 84]));
            bool gt = inb && (u > T);
            bool eq = inb && (u == T);
            unsigned bg = __ballot_sync(0xFFFFFFFFu, gt);
            if (bg) {
                int ldr = __ffs(bg) - 1; int bs = 0;
                if (lane == ldr && gt) bs = atomicAdd(&sh_misc[2], __popc(bg));
                bs = __shfl_sync(0xFFFFFFFFu, bs, ldr);
                if (gt) {
                    int pos = bs + __popc(bg & lt);
                    if (pos < KCAND) { cand_sc[pos] = u; cand_idx[pos] = (unsigned)i; }
                }
            }
            unsigned be = __ballot_sync(0xFFFFFFFFu, eq);
            if (be) {
                int ldr = __ffs(be) - 1; int bs = 0;
                if (lane == ldr && eq) bs = atomicAdd(&sh_misc[3], __popc(be));
                bs = __shfl_sync(0xFFFFFFFFu, bs, ldr);
                if (eq) {
                    int pos = bs + __popc(be & lt);
                    if (pos < KCAND) tie_idx[pos] = (unsigned)i;
                }
            }
        }
        __syncthreads();
        int nt = sh_misc[3];
        for (int s = threadIdx.x; s < KCAND; s += 512)
            if (s >= nt) tie_idx[s] = 0xFFFFFFFFu;
        __syncthreads();
        bitonic_u32_asc(tie_idx, KCAND);
        for (int s = threadIdx.x; s < KCAND; s += 512) {
            unsigned long long key;
            if (s < G) key = (((unsigned long long)cand_sc[s]) << 32) | (unsigned)(~cand_idx[s]);
            else       key = (((unsigned long long)T) << 32)          | (unsigned)(~tie_idx[s - G]);
            sh_key[s] = key;
        }
        __syncthreads();
        bitonic_u64_desc(sh_key, KCAND);
    }

    // ---- gather boxes (float4 + area) ----
    for (int s = threadIdx.x; s < KCAND; s += 512) {
        unsigned idx = ~((unsigned)(sh_key[s] & 0xFFFFFFFFull));
        float4 bx = g_boxes[b * A_TOT + (int)idx];
        sh_box[s] = bx;
        sh_ar[s] = fmaxf(bx.z - bx.x, 0.f) * fmaxf(bx.w - bx.y, 0.f);
    }
    __syncthreads();

    // ---- IoU suppression bitmask (2 LDS per j: float4 + area) ----
    for (int task = threadIdx.x; task < KCAND * 16; task += 512) {
        int w = task >> 9;
        int i = task & 511;
        int j0 = w << 5;
        unsigned bits = 0;
        if (j0 + 31 > i) {
            float4 bi = sh_box[i]; float ia = sh_ar[i];
            #pragma unroll 8
            for (int jj = 0; jj < 32; jj++) {
                int j = j0 + jj;
                if (j > i) {
                    float4 bj = sh_box[j];
                    float ih = fmaxf(fminf(bi.z, bj.z) - fmaxf(bi.x, bj.x), 0.f);
                    float iw = fmaxf(fminf(bi.w, bj.w) - fmaxf(bi.y, bj.y), 0.f);
                    float inter = ih * iw;
                    if (inter > 0.f) {
                        float un = ia + sh_ar[j] - inter;
                        if (un > 0.f && inter / un > 0.5f) bits |= (1u << jj);
                    }
                }
            }
        }
        sh_mask[i * 16 + w] = bits;
    }
    __syncthreads();

    // ---- blocked greedy NMS: word-serial in registers + parallel cross-word apply ----
    if (threadIdx.x < 16) {
        int l = threadIdx.x;
        unsigned keep = 0;
        #pragma unroll
        for (int t = 0; t < 32; t++) {
            float scf = __uint_as_float((unsigned)(sh_key[l * 32 + t] >> 32));
            if (scf > 0.05f) keep |= (1u << t);
        }
        for (int w0 = 0; w0 < 16; w0++) {
            if (l == w0) {
                #pragma unroll
                for (int ch = 0; ch < 4; ch++) {
                    unsigned m[8];
                    #pragma unroll
                    for (int t = 0; t < 8; t++)
                        m[t] = sh_mask[(w0 * 32 + ch * 8 + t) * 16 + w0];
                    #pragma unroll
                    for (int t = 0; t < 8; t++) {
                        int bit = ch * 8 + t;
                        if ((keep >> bit) & 1u) keep &= ~m[t];
                    }
                }
            }
            unsigned kw = __shfl_sync(0xFFFFu, keep, w0);
            unsigned acc = 0;
            #pragma unroll
            for (int ch = 0; ch < 4; ch++) {
                unsigned m[8];
                #pragma unroll
                for (int t = 0; t < 8; t++)
                    m[t] = sh_mask[(w0 * 32 + ch * 8 + t) * 16 + l];
                #pragma unroll
                for (int t = 0; t < 8; t++)
                    acc |= m[t] & (0u - ((kw >> (ch * 8 + t)) & 1u));
            }
            keep &= ~acc;
        }
        sh_keep[l] = keep;
    }
    __syncthreads();

    // ---- emit per-class top-100 (kept in score order, then suppressed) ----
    int nk = 0;
    for (int w = 0; w < 16; w++) nk += __popc(sh_keep[w]);
    for (int s = threadIdx.x; s < KCAND; s += 512) {
        int w = s >> 5, bpos = s & 31;
        unsigned kw = sh_keep[w];
        bool kept = (kw >> bpos) & 1u;
        int pre = 0;
        for (int q = 0; q < w; q++) pre += __popc(sh_keep[q]);
        pre += __popc(kw & ((1u << bpos) - 1u));
        int r = kept ? pre : (nk + (s - pre));
        if (r < MAXPC) {
            float scf = __uint_as_float((unsigned)(sh_key[s] >> 32));
            int ob = (b * NCLS + c) * MAXPC + r;
            g_cls_scores[ob] = kept ? scf : 0.0f;
            g_cls_boxes[ob] = sh_box[s];
        }
    }

    // reset counter for next replay (every thread read n before the first barrier)
    if (threadIdx.x == 0) g_cand_cnt[bc] = 0;
}

// ---------------- kernel 3: combine (per batch), 1024 threads ----------------
__global__ void __launch_bounds__(1024) k_combine(float* __restrict__ out, int out_size) {
    __shared__ unsigned int csh[256 + 128 + 128 + 512];
    __shared__ unsigned int tsort[512];
    __shared__ unsigned long long ckey[128];
    __shared__ int cmisc[8];
    unsigned int* hist     = csh;
    unsigned int* cand_sc  = csh + 256;
    unsigned int* cand_idx = csh + 384;
    unsigned int* tie      = csh + 512;

    int b = blockIdx.x;
    const float* sc = g_cls_scores + b * (NCLS * MAXPC);
    const int N = NCLS * MAXPC;
    const int NP = 8192;

    int lane = threadIdx.x & 31;
    unsigned lt = (1u << lane) - 1u;

    int E;
    unsigned T = radix_select_topk(sc, 1, false, N, NP, MAXPC, hist, cmisc, &E);
    int G = MAXPC - E;

    if (threadIdx.x == 0) { cmisc[2] = 0; cmisc[3] = 0; cmisc[4] = 0; }
    __syncthreads();
    for (int i = threadIdx.x; i < NP; i += 1024) {
        unsigned u = 0; bool inb = i < N;
        if (inb) u = __float_as_uint(sc[i]);
        bool gt = inb && (u > T);
        bool eq = inb && (u == T);
        unsigned bg = __ballot_sync(0xFFFFFFFFu, gt);
        if (bg) {
            int ldr = __ffs(bg) - 1; int bs = 0;
            if (lane == ldr && gt) bs = atomicAdd(&cmisc[2], __popc(bg));
            bs = __shfl_sync(0xFFFFFFFFu, bs, ldr);
            if (gt) {
                int pos = bs + __popc(bg & lt);
                if (pos < 128) { cand_sc[pos] = u; cand_idx[pos] = (unsigned)i; }
            }
        }
        unsigned be = __ballot_sync(0xFFFFFFFFu, eq);
        if (be) {
            int ldr = __ffs(be) - 1; int bs = 0;
            if (lane == ldr && eq) bs = atomicAdd(&cmisc[3], __popc(be));
            bs = __shfl_sync(0xFFFFFFFFu, bs, ldr);
            if (eq) {
                int pos = bs + __popc(be & lt);
                if (pos < 512) tie[pos] = (unsigned)i;
            }
        }
    }
    __syncthreads();
    int nt = min(cmisc[3], 512);
    for (int s = threadIdx.x; s < nt; s += 1024) {
        unsigned v = tie[s];
        int rk = 0;
        for (int q = 0; q < nt; q++) rk += (tie[q] < v);
        tsort[rk] = v;
    }
    __syncthreads();

    for (int s = threadIdx.x; s < 128; s += 1024) {
        unsigned long long key;
        if (s < G)           key = (((unsigned long long)cand_sc[s]) << 32) | (unsigned)(~cand_idx[s]);
        else if (s < MAXPC)  key = (((unsigned long long)T) << 32)          | (unsigned)(~tsort[s - G]);
        else                 key = 0ull;
        ckey[s] = key;
    }
    __syncthreads();
    bitonic_u64_desc(ckey, 128);

    int r = threadIdx.x;
    if (r < MAXPC) {
        unsigned long long kk = ckey[r];
        float s = __uint_as_float((unsigned)(kk >> 32));
        bool valid = s > 0.0f;
        float b0 = 0.f, b1 = 0.f, b2 = 0.f, b3 = 0.f, cls = 0.f, so = 0.f;
        if (valid) {
            unsigned f = ~((unsigned)(kk & 0xFFFFFFFFull));
            int ci = (int)f / MAXPC;
            float4 bb = g_cls_boxes[b * N + (int)f];
            b0 = fminf(fmaxf(bb.x, 0.f), 1.f);
            b1 = fminf(fmaxf(bb.y, 0.f), 1.f);
            b2 = fminf(fmaxf(bb.z, 0.f), 1.f);
            b3 = fminf(fmaxf(bb.w, 0.f), 1.f);
            cls = (float)ci;
            so = s;
            atomicAdd(&cmisc[4], 1);
        }
        int ob = (b * MAXPC + r) * 4;
        if (ob + 3 < out_size) {
            out[ob + 0] = b0; out[ob + 1] = b1; out[ob + 2] = b2; out[ob + 3] = b3;
        }
        int os = BATCH * MAXPC * 4 + b * MAXPC + r;
        if (os < out_size) out[os] = so;
        int oc = BATCH * MAXPC * 4 + BATCH * MAXPC + b * MAXPC + r;
        if (oc < out_size) out[oc] = cls;
    }
    __syncthreads();
    if (threadIdx.x == 0) {
        int ov = BATCH * MAXPC * 4 + 2 * BATCH * MAXPC + b;
        if (ov < out_size) out[ov] = (float)cmisc[4];
    }
}

// ---------------- launch ----------------
extern "C" void kernel_launch(void* const* d_in, const int* in_sizes, int n_in,
                              void* d_out, int out_size) {
    const float* pred;
    if (n_in >= 2 && in_sizes[0] == BATCH * A_TOT * 84) pred = (const float*)d_in[0];
    else                                                pred = (const float*)d_in[1];
    float* out = (float*)d_out;

    k_dims<<<1, 64>>>();
    k_decode<<<1184, 512>>>((const float4*)pred);
    k_nms<<<BATCH * NCLS, 512>>>(pred);
    k_combine<<<BATCH, 1024>>>(out, out_size);
}

// round 11
// speedup vs baseline: 6.0797x; 1.0096x over previous
#include <cuda_runtime.h>
#include <cstdint>

#define BATCH 4
#define A_TOT 76725
#define A_PAD 76800
#define NCLS  80
#define KCAND 512
#define MAXPC 100
#define CAP   1024
#define AG_TOT (BATCH * A_TOT)        // 306900 anchors total
#define NSC (AG_TOT * 20)             // score chunks (float4) total
// logit(0.91) = ln(0.91/0.09)
#define LOGIT_T0 2.3136349f

// ---------------- scratch (device globals; statically zero-initialized) ----------------
__device__ float4 g_boxes[BATCH * A_TOT];                     // decoded [x,y,w,h]
__device__ uint2  g_cand[BATCH * NCLS * CAP];                 // (score_bits, anchor_idx)
__device__ int    g_cand_cnt[BATCH * NCLS];                   // zero-init; k_nms resets after use
__device__ float  g_cls_scores[BATCH * NCLS * MAXPC];
__device__ float4 g_cls_boxes[BATCH * NCLS * MAXPC];
__device__ float  g_dims[45 * 2];                             // per (level,k): w,h

// ---------------- helpers ----------------
__device__ __forceinline__ float sigmoid_f(float x) {
    if (x >= 0.f) { float z = expf(-x); return 1.f / (1.f + z); }
    float z = expf(x); return z / (1.f + z);
}

// generic (fully-barriered) bitonic sorts — used on rare fallback paths only
__device__ void bitonic_u64_desc(unsigned long long* key, int n) {
    for (int k = 2; k <= n; k <<= 1) {
        for (int j = k >> 1; j > 0; j >>= 1) {
            for (int idx = threadIdx.x; idx < n; idx += blockDim.x) {
                int p = idx ^ j;
                if (p > idx) {
                    unsigned long long a = key[idx], b = key[p];
                    bool up = ((idx & k) == 0);
                    bool sw = up ? (a < b) : (a > b);
                    if (sw) { key[idx] = b; key[p] = a; }
                }
            }
            __syncthreads();
        }
    }
}

__device__ void bitonic_u32_asc(unsigned int* key, int n) {
    for (int k = 2; k <= n; k <<= 1) {
        for (int j = k >> 1; j > 0; j >>= 1) {
            for (int idx = threadIdx.x; idx < n; idx += blockDim.x) {
                int p = idx ^ j;
                if (p > idx) {
                    unsigned int a = key[idx], b = key[p];
                    bool up = ((idx & k) == 0);
                    bool sw = up ? (a > b) : (a < b);
                    if (sw) { key[idx] = b; key[p] = a; }
                }
            }
            __syncthreads();
        }
    }
}

// barrier-lite bitonic: with layout idx = tid + m*blockDim (blockDim % 32 == 0),
// every warp owns aligned 32-element chunks, so phases with j < 32 are warp-local.
// Block barrier only when the phase (or the next phase) crosses warps.
__device__ void bitonic_u64_desc_ws(unsigned long long* key, int n) {
    for (int k = 2; k <= n; k <<= 1) {
        for (int j = k >> 1; j > 0; j >>= 1) {
            for (int idx = threadIdx.x; idx < n; idx += blockDim.x) {
                int p = idx ^ j;
                if (p > idx) {
                    unsigned long long a = key[idx], b = key[p];
                    bool up = ((idx & k) == 0);
                    bool sw = up ? (a < b) : (a > b);
                    if (sw) { key[idx] = b; key[p] = a; }
                }
            }
            if (j >= 32 || (j == 1 && k >= 32 && (k << 1) <= n)) __syncthreads();
            else __syncwarp();
        }
    }
    __syncthreads();
}

// warp-parallel "pick threshold bucket" over a 256-bin shared histogram.
__device__ __forceinline__ void pick_bucket(unsigned* hist, int* misc, int K) {
    if (threadIdx.x < 32) {
        int l = threadIdx.x;
        int base = 255 - l * 8;
        unsigned hv[8]; unsigned t = 0;
        #pragma unroll
        for (int q = 0; q < 8; q++) { hv[q] = hist[base - q]; t += hv[q]; }
        unsigned p = t;
        #pragma unroll
        for (int o = 1; o < 32; o <<= 1) {
            unsigned v = __shfl_up_sync(0xFFFFFFFFu, p, o);
            if (l >= o) p += v;
        }
        unsigned excl = p - t;
        bool has = (excl < (unsigned)K) && ((unsigned)K <= excl + t);
        unsigned bal = __ballot_sync(0xFFFFFFFFu, has);
        int ldr = __ffs(bal) - 1;
        if (l == ldr) {
            unsigned cum = excl; int chosen = base;
            #pragma unroll
            for (int q = 0; q < 8; q++) {
                if (cum + hv[q] >= (unsigned)K) { chosen = base - q; break; }
                cum += hv[q];
            }
            misc[0] = chosen; misc[1] = (int)cum;
        }
    }
    __syncthreads();
}

// 4-pass radix select; returns bits of K-th largest; *E_out = #ties in top-K.
__device__ unsigned radix_select_topk(const float* base, int stride, bool sig,
                                      int N, int Npad, int K,
                                      unsigned* hist, int* misc, int* E_out) {
    unsigned prefix = 0;
    int lane = threadIdx.x & 31;
    unsigned lt = (1u << lane) - 1u;
    for (int pass = 0; pass < 4; pass++) {
        int shift = 24 - 8 * pass;
        for (int i = threadIdx.x; i < 256; i += blockDim.x) hist[i] = 0;
        __syncthreads();
        unsigned himask = pass ? (0xFFFFFFFFu << (shift + 8)) : 0u;
        for (int i = threadIdx.x; i < Npad; i += blockDim.x) {
            unsigned u = 0; bool ok = false;
            if (i < N) {
                float v = base[(size_t)i * stride];
                if (sig) v = sigmoid_f(v);
                u = __float_as_uint(v);
                ok = (pass == 0) || ((u & himask) == prefix);
            }
            unsigned bk = ok ? ((u >> shift) & 0xFFu) : (0x200u + (unsigned)lane);
            unsigned peers = __match_any_sync(0xFFFFFFFFu, bk);
            if (ok && ((peers & lt) == 0u)) atomicAdd(&hist[bk], (unsigned)__popc(peers));
        }
        __syncthreads();
        pick_bucket(hist, misc, K);
        K -= misc[1];
        prefix |= ((unsigned)misc[0]) << shift;
        __syncthreads();
    }
    *E_out = K;
    return prefix;
}

// ---------------- kernel 0: anchor dims table (double precision, matches numpy) ----------------
__global__ void k_dims() {
    int t = threadIdx.x;
    if (t < 45) {
        int lvl = t / 9, k = t % 9;
        int ri = k / 3, si = k % 3;
        double r = (ri == 0) ? 0.5 : (ri == 1 ? 1.0 : 2.0);
        double s = pow(2.0, (double)si / 3.0);
        double side = (double)(1 << (lvl + 5));       // 2^(level+2), level = lvl+3
        double area = side * side;
        double ah = sqrt(area / r);
        double aw = area / ah;
        g_dims[t * 2 + 0] = (float)(s * aw);
        g_dims[t * 2 + 1] = (float)(s * ah);
    }
}

// ---------------- kernel 1a: score scan (uniform warps, no box path) ----------------
// iterate over the AG_TOT*20 score chunks; chunk s -> anchor ag = s/20, chunk ch = s%20,
// memory address = ag*21 + ch (skips each anchor's box chunk).
__global__ void __launch_bounds__(512) k_scores(const float4* __restrict__ pred4) {
    int S = gridDim.x * blockDim.x;
    int tid = blockIdx.x * blockDim.x + threadIdx.x;

    for (int base = tid; base < NSC; base += 4 * S) {
        int s[4]; int ag[4]; float4 v[4]; bool ok[4];
        #pragma unroll
        for (int t = 0; t < 4; t++) {
            s[t] = base + t * S;
            ok[t] = s[t] < NSC;
            if (ok[t]) {
                ag[t] = s[t] / 20;                       // mul-shift (constant divisor)
                v[t] = pred4[ag[t] * 21 + (s[t] - ag[t] * 20)];
            }
        }
        #pragma unroll
        for (int t = 0; t < 4; t++) {
            if (!ok[t]) continue;
            float mx = fmaxf(fmaxf(v[t].x, v[t].y), fmaxf(v[t].z, v[t].w));
            if (mx > LOGIT_T0) {
                int ch = s[t] - ag[t] * 20;
                int b = ag[t] / A_TOT;
                unsigned a = (unsigned)(ag[t] - b * A_TOT);
                float sv[4] = {v[t].x, v[t].y, v[t].z, v[t].w};
                #pragma unroll
                for (int j = 0; j < 4; j++) {
                    if (sv[j] > LOGIT_T0) {
                        int c = ch * 4 + j;
                        int slot = atomicAdd(&g_cand_cnt[b * NCLS + c], 1);
                        if (slot < CAP)
                            g_cand[(b * NCLS + c) * CAP + slot] =
                                make_uint2(__float_as_uint(sigmoid_f(sv[j])), a);
                    }
                }
            }
        }
    }
}

// ---------------- kernel 1b: box decode (one thread per anchor; uniform warps) ----------------
__global__ void __launch_bounds__(512) k_boxes(const float4* __restrict__ pred4) {
    int ag = blockIdx.x * blockDim.x + threadIdx.x;
    if (ag >= AG_TOT) return;
    float4 v = pred4[ag * 21 + 20];

    int b = ag / A_TOT;
    int a = ag - b * A_TOT;
    int lvl, rem, fw;
    if      (a < 57600) { lvl = 0; rem = a;          fw = 80; }
    else if (a < 72000) { lvl = 1; rem = a - 57600;  fw = 40; }
    else if (a < 75600) { lvl = 2; rem = a - 72000;  fw = 20; }
    else if (a < 76500) { lvl = 3; rem = a - 75600;  fw = 10; }
    else                { lvl = 4; rem = a - 76500;  fw = 5;  }
    int k = rem % 9, cell = rem / 9;
    int x = cell % fw, y = cell / fw;
    float aw = g_dims[(lvl * 9 + k) * 2 + 0];
    float ah = g_dims[(lvl * 9 + k) * 2 + 1];
    float stride = (float)(8 << lvl);
    float acx = ((float)x + 0.5f) * stride;
    float acy = ((float)y + 0.5f) * stride;
    float bp0 = v.x * 0.1f;
    float bp1 = v.y * 0.1f;
    float bp2 = v.z * 0.2f;
    float bp3 = v.w * 0.2f;
    float4 o;
    o.x = bp0 * aw + acx;
    o.y = bp1 * ah + acy;
    o.z = expf(bp2) * aw;
    o.w = expf(bp3) * ah;
    g_boxes[ag] = o;
}

// ---------------- kernel 2: per-(b,c) top-512 + NMS + per-class top-100 ----------------
__global__ void __launch_bounds__(512) k_nms(const float* __restrict__ pred) {
    __shared__ __align__(16) unsigned int sh_mask[KCAND * 16];  // 32 KB (overlaid scratch)
    __shared__ unsigned long long sh_key[KCAND];                // 4 KB
    __shared__ __align__(16) float4 sh_box[KCAND];              // 8 KB
    __shared__ float sh_ar[KCAND];                              // 2 KB
    __shared__ unsigned int sh_keep[16];
    __shared__ int sh_misc[8];

    int bc = blockIdx.x;
    int b = bc / NCLS, c = bc % NCLS;
    int lane = threadIdx.x & 31;
    unsigned lt = (1u << lane) - 1u;

    int n = g_cand_cnt[bc];

    if (n >= KCAND && n <= CAP) {
        // -------- fast path: sort the <=1024 prefiltered candidates --------
        unsigned long long* buf = (unsigned long long*)sh_mask;   // 1024 u64 = 8 KB
        for (int s = threadIdx.x; s < CAP; s += 512) {
            unsigned long long key = 0ull;
            if (s < n) {
                uint2 r = g_cand[bc * CAP + s];
                key = (((unsigned long long)r.x) << 32) | (unsigned)(~r.y);
            }
            buf[s] = key;
        }
        __syncthreads();
        bitonic_u64_desc_ws(buf, CAP);
        for (int s = threadIdx.x; s < KCAND; s += 512) sh_key[s] = buf[s];
        __syncthreads();
    } else {
        // -------- fallback (statistically never taken; exact & correct) --------
        unsigned int* hist     = sh_mask;
        unsigned int* cand_sc  = sh_mask + 256;
        unsigned int* cand_idx = sh_mask + 768;
        unsigned int* tie_idx  = sh_mask + 1280;
        const float* sbase = pred + (size_t)b * A_TOT * 84 + c;

        int E;
        unsigned T = radix_select_topk(sbase, 84, true, A_TOT, A_PAD, KCAND, hist, sh_misc, &E);
        int G = KCAND - E;

        if (threadIdx.x == 0) { sh_misc[2] = 0; sh_misc[3] = 0; }
        __syncthreads();
        for (int i = threadIdx.x; i < A_PAD; i += 512) {
            unsigned u = 0; bool inb = i < A_TOT;
            if (inb) u = __float_as_uint(sigmoid_f(sbase[(size_t)i * 84]));
            bool gt = inb && (u > T);
            bool eq = inb && (u == T);
            unsigned bg = __ballot_sync(0xFFFFFFFFu, gt);
            if (bg) {
                int ldr = __ffs(bg) - 1; int bs = 0;
                if (lane == ldr && gt) bs = atomicAdd(&sh_misc[2], __popc(bg));
                bs = __shfl_sync(0xFFFFFFFFu, bs, ldr);
                if (gt) {
                    int pos = bs + __popc(bg & lt);
                    if (pos < KCAND) { cand_sc[pos] = u; cand_idx[pos] = (unsigned)i; }
                }
            }
            unsigned be = __ballot_sync(0xFFFFFFFFu, eq);
            if (be) {
                int ldr = __ffs(be) - 1; int bs = 0;
                if (lane == ldr && eq) bs = atomicAdd(&sh_misc[3], __popc(be));
                bs = __shfl_sync(0xFFFFFFFFu, bs, ldr);
                if (eq) {
                    int pos = bs + __popc(be & lt);
                    if (pos < KCAND) tie_idx[pos] = (unsigned)i;
                }
            }
        }
        __syncthreads();
        int nt = sh_misc[3];
        for (int s = threadIdx.x; s < KCAND; s += 512)
            if (s >= nt) tie_idx[s] = 0xFFFFFFFFu;
        __syncthreads();
        bitonic_u32_asc(tie_idx, KCAND);
        for (int s = threadIdx.x; s < KCAND; s += 512) {
            unsigned long long key;
            if (s < G) key = (((unsigned long long)cand_sc[s]) << 32) | (unsigned)(~cand_idx[s]);
            else       key = (((unsigned long long)T) << 32)          | (unsigned)(~tie_idx[s - G]);
            sh_key[s] = key;
        }
        __syncthreads();
        bitonic_u64_desc(sh_key, KCAND);
        __syncthreads();
    }

    // ---- gather boxes (float4 + area) ----
    for (int s = threadIdx.x; s < KCAND; s += 512) {
        unsigned idx = ~((unsigned)(sh_key[s] & 0xFFFFFFFFull));
        float4 bx = g_boxes[b * A_TOT + (int)idx];
        sh_box[s] = bx;
        sh_ar[s] = fmaxf(bx.z - bx.x, 0.f) * fmaxf(bx.w - bx.y, 0.f);
    }
    __syncthreads();

    // ---- IoU suppression bitmask (2 LDS per j: float4 + area) ----
    for (int task = threadIdx.x; task < KCAND * 16; task += 512) {
        int w = task >> 9;
        int i = task & 511;
        int j0 = w << 5;
        unsigned bits = 0;
        if (j0 + 31 > i) {
            float4 bi = sh_box[i]; float ia = sh_ar[i];
            #pragma unroll 8
            for (int jj = 0; jj < 32; jj++) {
                int j = j0 + jj;
                if (j > i) {
                    float4 bj = sh_box[j];
                    float ih = fmaxf(fminf(bi.z, bj.z) - fmaxf(bi.x, bj.x), 0.f);
                    float iw = fmaxf(fminf(bi.w, bj.w) - fmaxf(bi.y, bj.y), 0.f);
                    float inter = ih * iw;
                    if (inter > 0.f) {
                        float un = ia + sh_ar[j] - inter;
                        if (un > 0.f && inter / un > 0.5f) bits |= (1u << jj);
                    }
                }
            }
        }
        sh_mask[i * 16 + w] = bits;
    }
    __syncthreads();

    // ---- blocked greedy NMS: word-serial in registers + parallel cross-word apply ----
    if (threadIdx.x < 16) {
        int l = threadIdx.x;
        unsigned keep = 0;
        #pragma unroll
        for (int t = 0; t < 32; t++) {
            float scf = __uint_as_float((unsigned)(sh_key[l * 32 + t] >> 32));
            if (scf > 0.05f) keep |= (1u << t);
        }
        for (int w0 = 0; w0 < 16; w0++) {
            if (l == w0) {
                #pragma unroll
                for (int ch = 0; ch < 4; ch++) {
                    unsigned m[8];
                    #pragma unroll
                    for (int t = 0; t < 8; t++)
                        m[t] = sh_mask[(w0 * 32 + ch * 8 + t) * 16 + w0];
                    #pragma unroll
                    for (int t = 0; t < 8; t++) {
                        int bit = ch * 8 + t;
                        if ((keep >> bit) & 1u) keep &= ~m[t];
                    }
                }
            }
            unsigned kw = __shfl_sync(0xFFFFu, keep, w0);
            unsigned acc = 0;
            #pragma unroll
            for (int ch = 0; ch < 4; ch++) {
                unsigned m[8];
                #pragma unroll
                for (int t = 0; t < 8; t++)
                    m[t] = sh_mask[(w0 * 32 + ch * 8 + t) * 16 + l];
                #pragma unroll
                for (int t = 0; t < 8; t++)
                    acc |= m[t] & (0u - ((kw >> (ch * 8 + t)) & 1u));
            }
            keep &= ~acc;
        }
        sh_keep[l] = keep;
    }
    __syncthreads();

    // ---- emit per-class top-100 (kept in score order, then suppressed) ----
    int nk = 0;
    for (int w = 0; w < 16; w++) nk += __popc(sh_keep[w]);
    for (int s = threadIdx.x; s < KCAND; s += 512) {
        int w = s >> 5, bpos = s & 31;
        unsigned kw = sh_keep[w];
        bool kept = (kw >> bpos) & 1u;
        int pre = 0;
        for (int q = 0; q < w; q++) pre += __popc(sh_keep[q]);
        pre += __popc(kw & ((1u << bpos) - 1u));
        int r = kept ? pre : (nk + (s - pre));
        if (r < MAXPC) {
            float scf = __uint_as_float((unsigned)(sh_key[s] >> 32));
            int ob = (b * NCLS + c) * MAXPC + r;
            g_cls_scores[ob] = kept ? scf : 0.0f;
            g_cls_boxes[ob] = sh_box[s];
        }
    }

    // reset counter for next replay (every thread read n before the first barrier)
    if (threadIdx.x == 0) g_cand_cnt[bc] = 0;
}

// ---------------- kernel 3: combine (per batch), 1024 threads ----------------
__global__ void __launch_bounds__(1024) k_combine(float* __restrict__ out, int out_size) {
    __shared__ unsigned int csh[256 + 128 + 128 + 512];
    __shared__ unsigned int tsort[512];
    __shared__ unsigned long long ckey[128];
    __shared__ int cmisc[8];
    unsigned int* hist     = csh;
    unsigned int* cand_sc  = csh + 256;
    unsigned int* cand_idx = csh + 384;
    unsigned int* tie      = csh + 512;

    int b = blockIdx.x;
    const float* sc = g_cls_scores + b * (NCLS * MAXPC);
    const int N = NCLS * MAXPC;
    const int NP = 8192;

    int lane = threadIdx.x & 31;
    unsigned lt = (1u << lane) - 1u;

    int E;
    unsigned T = radix_select_topk(sc, 1, false, N, NP, MAXPC, hist, cmisc, &E);
    int G = MAXPC - E;

    if (threadIdx.x == 0) { cmisc[2] = 0; cmisc[3] = 0; cmisc[4] = 0; }
    __syncthreads();
    for (int i = threadIdx.x; i < NP; i += 1024) {
        unsigned u = 0; bool inb = i < N;
        if (inb) u = __float_as_uint(sc[i]);
        bool gt = inb && (u > T);
        bool eq = inb && (u == T);
        unsigned bg = __ballot_sync(0xFFFFFFFFu, gt);
        if (bg) {
            int ldr = __ffs(bg) - 1; int bs = 0;
            if (lane == ldr && gt) bs = atomicAdd(&cmisc[2], __popc(bg));
            bs = __shfl_sync(0xFFFFFFFFu, bs, ldr);
            if (gt) {
                int pos = bs + __popc(bg & lt);
                if (pos < 128) { cand_sc[pos] = u; cand_idx[pos] = (unsigned)i; }
            }
        }
        unsigned be = __ballot_sync(0xFFFFFFFFu, eq);
        if (be) {
            int ldr = __ffs(be) - 1; int bs = 0;
            if (lane == ldr && eq) bs = atomicAdd(&cmisc[3], __popc(be));
            bs = __shfl_sync(0xFFFFFFFFu, bs, ldr);
            if (eq) {
                int pos = bs + __popc(be & lt);
                if (pos < 512) tie[pos] = (unsigned)i;
            }
        }
    }
    __syncthreads();
    int nt = min(cmisc[3], 512);
    for (int s = threadIdx.x; s < nt; s += 1024) {
        unsigned v = tie[s];
        int rk = 0;
        for (int q = 0; q < nt; q++) rk += (tie[q] < v);
        tsort[rk] = v;
    }
    __syncthreads();

    for (int s = threadIdx.x; s < 128; s += 1024) {
        unsigned long long key;
        if (s < G)           key = (((unsigned long long)cand_sc[s]) << 32) | (unsigned)(~cand_idx[s]);
        else if (s < MAXPC)  key = (((unsigned long long)T) << 32)          | (unsigned)(~tsort[s - G]);
        else                 key = 0ull;
        ckey[s] = key;
    }
    __syncthreads();
    bitonic_u64_desc_ws(ckey, 128);

    int r = threadIdx.x;
    if (r < MAXPC) {
        unsigned long long kk = ckey[r];
        float s = __uint_as_float((unsigned)(kk >> 32));
        bool valid = s > 0.0f;
        float b0 = 0.f, b1 = 0.f, b2 = 0.f, b3 = 0.f, cls = 0.f, so = 0.f;
        if (valid) {
            unsigned f = ~((unsigned)(kk & 0xFFFFFFFFull));
            int ci = (int)f / MAXPC;
            float4 bb = g_cls_boxes[b * N + (int)f];
            b0 = fminf(fmaxf(bb.x, 0.f), 1.f);
            b1 = fminf(fmaxf(bb.y, 0.f), 1.f);
            b2 = fminf(fmaxf(bb.z, 0.f), 1.f);
            b3 = fminf(fmaxf(bb.w, 0.f), 1.f);
            cls = (float)ci;
            so = s;
            atomicAdd(&cmisc[4], 1);
        }
        int ob = (b * MAXPC + r) * 4;
        if (ob + 3 < out_size) {
            out[ob + 0] = b0; out[ob + 1] = b1; out[ob + 2] = b2; out[ob + 3] = b3;
        }
        int os = BATCH * MAXPC * 4 + b * MAXPC + r;
        if (os < out_size) out[os] = so;
        int oc = BATCH * MAXPC * 4 + BATCH * MAXPC + b * MAXPC + r;
        if (oc < out_size) out[oc] = cls;
    }
    __syncthreads();
    if (threadIdx.x == 0) {
        int ov = BATCH * MAXPC * 4 + 2 * BATCH * MAXPC + b;
        if (ov < out_size) out[ov] = (float)cmisc[4];
    }
}

// ---------------- launch ----------------
extern "C" void kernel_launch(void* const* d_in, const int* in_sizes, int n_in,
                              void* d_out, int out_size) {
    const float* pred;
    if (n_in >= 2 && in_sizes[0] == BATCH * A_TOT * 84) pred = (const float*)d_in[0];
    else                                                pred = (const float*)d_in[1];
    float* out = (float*)d_out;

    k_dims<<<1, 64>>>();
    k_scores<<<1184, 512>>>((const float4*)pred);
    k_boxes<<<(AG_TOT + 511) / 512, 512>>>((const float4*)pred);
    k_nms<<<BATCH * NCLS, 512>>>(pred);
    k_combine<<<BATCH, 1024>>>(out, out_size);
}